// round 14
// baseline (speedup 1.0000x reference)
#include <cuda_runtime.h>
#include <cuda_bf16.h>
#include <stdint.h>

#define TT   4
#define NN   20000
#define EE   320000
#define FF   64
#define HH   64
#define TSN  50
#define G4H  256
#define KX   128     // aggx(64) | xn(64)
#define KH   64      // aggh
#define KSEL 10000
#define BK   16
#define KCH  157     // Ggemm K-chunk: 128 splits * 157 >= 20000

// ---------------- device scratch (zero-initialized at load) ----------------
__device__ __align__(16) float g_X[(long)TT * NN * KX];
__device__ __align__(16) float g_P[(long)TT * NN * G4H];
__device__ __align__(16) float g_AH[NN * KH];
__device__ __align__(16) float g_h[NN * HH];
__device__ __align__(16) float g_c[NN * HH];
__device__ float g_dinv[NN];
__device__ float g_self[NN];
__device__ __align__(16) int g_cnt[NN];
__device__ int   g_cursor[NN];
__device__ int   g_rowptr[NN + 1];
__device__ int   g_src[EE];
__device__ int   g_dst[EE];
__device__ int   g_s_src[EE];
__device__ int   g_s_eid[EE];
__device__ float g_s_gcn[EE];
__device__ __align__(16) unsigned g_Wxp_hi[(KX / 2) * G4H];
__device__ __align__(16) unsigned g_Wxp_lo[(KX / 2) * G4H];
__device__ __align__(16) unsigned g_Wgp_hi[(KH / 2) * G4H];
__device__ __align__(16) unsigned g_Wgp_lo[(KH / 2) * G4H];
__device__ __align__(16) float g_bc[G4H];
__device__ float g_colsum[TT * FF];
__device__ float g_colsq[TT * FF];
__device__ float g_mean[TT * FF];
__device__ float g_rinv[TT * FF];
__device__ float g_v[HH];
__device__ float g_raw[NN];
__device__ float g_sig[NN];
__device__ unsigned g_key[NN];
__device__ float g_high[HH];
__device__ __align__(16) float g_G[TSN * G4H];
__device__ float g_hl[HH];
__device__ unsigned g_prefix;
__device__ unsigned g_kkleft;
__device__ unsigned g_ticket;
__device__ unsigned g_cs_ticket[TT];
__device__ unsigned g_sc_ticket;
__device__ float g_ssum, g_ssq, g_smean, g_sinv, g_ploss;

__device__ __forceinline__ float sigm(float x) { return 1.f / (1.f + expf(-x)); }

// split (a,b) into packed bf16x2 hi + lo (2-term bf16 split; drops only lo*lo ~2^-18)
__device__ __forceinline__ void bf16split2(float a, float b, unsigned& hi, unsigned& lo) {
    __nv_bfloat16 ah = __float2bfloat16_rn(a);
    __nv_bfloat16 bh = __float2bfloat16_rn(b);
    float ar = a - __bfloat162float(ah);
    float br = b - __bfloat162float(bh);
    __nv_bfloat162 H; H.x = ah; H.y = bh;
    __nv_bfloat162 L; L.x = __float2bfloat16_rn(ar); L.y = __float2bfloat16_rn(br);
    hi = *(unsigned*)&H;
    lo = *(unsigned*)&L;
}

#define MMA_BF16(c0, c1, c2, c3, a0, a1, a2, a3, b0, b1)                         \
    asm volatile("mma.sync.aligned.m16n8k16.row.col.f32.bf16.bf16.f32 "          \
                 "{%0,%1,%2,%3}, {%4,%5,%6,%7}, {%8,%9}, {%0,%1,%2,%3};"         \
                 : "+f"(c0), "+f"(c1), "+f"(c2), "+f"(c3)                        \
                 : "r"(a0), "r"(a1), "r"(a2), "r"(a3), "r"(b0), "r"(b1))

// ---------------- branch B0: decode edges (+count) + copy h0/c0 ----------------
__global__ void k_decode(const void* eiraw, const float* __restrict__ h0,
                         const float* __restrict__ c0) {
    int gid = blockIdx.x * blockDim.x + threadIdx.x;   // exactly EE threads
    const long long* p64 = (const long long*)eiraw;
    bool is64 = true;
#pragma unroll
    for (int j = 0; j < 8; j++) {
        long long v = p64[j];
        if (v < 0 || v >= NN) is64 = false;
    }
    int s, d;
    if (is64) { s = (int)p64[gid]; d = (int)p64[EE + gid]; }
    else { const int* p32 = (const int*)eiraw; s = p32[gid]; d = p32[EE + gid]; }
    s = min(max(s, 0), NN - 1);
    d = min(max(d, 0), NN - 1);
    g_src[gid] = s;
    g_dst[gid] = d;
    atomicAdd(&g_cnt[d], 1);
    for (int j = gid; j < NN * HH; j += EE) { g_h[j] = h0[j]; g_c[j] = c0[j]; }
}

// ---------------- branch B1: fast single-block prefix scan + node norms ----------------
__global__ void k_prefix() {
    __shared__ int wsum[32];
    int t = threadIdx.x, lane = t & 31, wid = t >> 5;
    int vals[20];
    int s = 0;
    if (t < 1000) {
        const int4* p = (const int4*)(g_cnt + t * 20);
#pragma unroll
        for (int i = 0; i < 5; i++) {
            int4 v = p[i];
            vals[i * 4 + 0] = v.x; vals[i * 4 + 1] = v.y;
            vals[i * 4 + 2] = v.z; vals[i * 4 + 3] = v.w;
            s += v.x + v.y + v.z + v.w;
        }
    }
    int x = s;
#pragma unroll
    for (int o = 1; o < 32; o <<= 1) {
        int y = __shfl_up_sync(0xffffffffu, x, o);
        if (lane >= o) x += y;
    }
    if (lane == 31) wsum[wid] = x;
    __syncthreads();
    if (wid == 0) {
        int sv = wsum[lane];
#pragma unroll
        for (int o = 1; o < 32; o <<= 1) {
            int y = __shfl_up_sync(0xffffffffu, sv, o);
            if (lane >= o) sv += y;
        }
        wsum[lane] = sv;
    }
    __syncthreads();
    int excl = x - s + (wid > 0 ? wsum[wid - 1] : 0);
    if (t < 1000) {
        int run = excl;
#pragma unroll
        for (int j = 0; j < 20; j++) {
            int idx = t * 20 + j;
            g_rowptr[idx] = run;
            int v = vals[j];
            run += v;
            float dd = (float)v + 1.f;
            g_dinv[idx] = rsqrtf(dd);
            g_self[idx] = 1.f / dd;
            g_cnt[idx] = 0;   // reset for next replay
        }
    }
    if (t == 1023) g_rowptr[NN] = excl;
}

// ---------------- branch B2: bucket edges by destination ----------------
__global__ void k_sortedges() {
    int e = blockIdx.x * blockDim.x + threadIdx.x;
    if (e >= EE) return;
    int s = g_src[e], d = g_dst[e];
    int pos = g_rowptr[d] + atomicAdd(&g_cursor[d], 1);
    g_s_src[pos] = s;
    g_s_eid[pos] = e;
    g_s_gcn[pos] = g_dinv[s] * g_dinv[d];
}

// ---------------- agg_h gather (one warp per node, 2-way unrolled for MLP) ----------------
__global__ void k_hgather() {
    int node = (blockIdx.x * blockDim.x + threadIdx.x) >> 5;
    int lane = threadIdx.x & 31;
    if (node >= NN) return;
    if (lane == 0) g_cursor[node] = 0;   // idempotent reset for next replay
    int beg = g_rowptr[node], end = g_rowptr[node + 1];
    float slf = g_self[node];
    float2 hv = ((const float2*)(g_h + (long)node * 64))[lane];
    float2 a0 = make_float2(slf * hv.x, slf * hv.y);
    float2 a1 = make_float2(0.f, 0.f);
    int e = beg;
    for (; e + 2 <= end; e += 2) {
        int s0 = g_s_src[e], s1 = g_s_src[e + 1];
        float gn0 = g_s_gcn[e], gn1 = g_s_gcn[e + 1];
        float2 v0 = ((const float2*)(g_h + (long)s0 * 64))[lane];
        float2 v1 = ((const float2*)(g_h + (long)s1 * 64))[lane];
        a0.x += gn0 * v0.x; a0.y += gn0 * v0.y;
        a1.x += gn1 * v1.x; a1.y += gn1 * v1.y;
    }
    if (e < end) {
        int s0 = g_s_src[e];
        float gn0 = g_s_gcn[e];
        float2 v0 = ((const float2*)(g_h + (long)s0 * 64))[lane];
        a0.x += gn0 * v0.x; a0.y += gn0 * v0.y;
    }
    a0.x += a1.x; a0.y += a1.y;
    ((float2*)(g_AH + (long)node * 64))[lane] = a0;
}

// ---------------- main A0: per-timestep column stats ----------------
__global__ void k_colstats(const float* __restrict__ xs) {
    __shared__ float ss[256], sq[256];
    __shared__ int islast;
    int t = blockIdx.y;
    const float* xt = xs + (long)t * NN * FF;
    int f = threadIdx.x & 63, slot = threadIdx.x >> 6;
    float s = 0.f, q = 0.f;
    for (int n = blockIdx.x * 4 + slot; n < NN; n += gridDim.x * 4) {
        float v = xt[n * 64 + f];
        s += v; q += v * v;
    }
    ss[threadIdx.x] = s; sq[threadIdx.x] = q;
    __syncthreads();
    if (slot == 0) {
        s = ss[f] + ss[f + 64] + ss[f + 128] + ss[f + 192];
        q = sq[f] + sq[f + 64] + sq[f + 128] + sq[f + 192];
        atomicAdd(&g_colsum[t * 64 + f], s);
        atomicAdd(&g_colsq[t * 64 + f], q);
    }
    __syncthreads();
    if (threadIdx.x == 0) {
        __threadfence();
        islast = (atomicAdd(&g_cs_ticket[t], 1u) == gridDim.x - 1);
    }
    __syncthreads();
    if (islast && threadIdx.x < 64) {
        int o = t * 64 + threadIdx.x;
        float fs = atomicAdd(&g_colsum[o], 0.f);
        float fq = atomicAdd(&g_colsq[o], 0.f);
        float mean = fs * (1.f / NN);
        float var = (fq - fs * fs * (1.f / NN)) * (1.f / (NN - 1));
        g_mean[o] = mean;
        g_rinv[o] = 1.f / (sqrtf(fmaxf(var, 0.f)) + 1e-6f);
        g_colsum[o] = 0.f;
        g_colsq[o] = 0.f;
        if (threadIdx.x == 0) g_cs_ticket[t] = 0u;
    }
}

// ---------------- main A1: normalize x (all T) + pack/split weights ----------------
__global__ void k_prep(const float* __restrict__ xs,
                       const float* __restrict__ Wrel, const float* __restrict__ brel,
                       const float* __restrict__ Wroot, const float* __restrict__ Wg,
                       const float* __restrict__ bg) {
    int gid = blockIdx.x * blockDim.x + threadIdx.x;   // TT*NN*FF threads
    int t = gid / (NN * FF);
    int rem = gid - t * (NN * FF);
    int n = rem >> 6, f = rem & 63;
    float xn = (xs[gid] - g_mean[t * 64 + f]) * g_rinv[t * 64 + f];
    g_X[((long)t * NN + n) * KX + 64 + f] = xn;

    if (gid < (KX / 2) * G4H) {
        int kp = gid >> 8, col = gid & 255;
        int g = col >> 6, h2 = col & 63;
        int k0 = 2 * kp, k1 = 2 * kp + 1;
        float w0 = (k0 < 64) ? Wrel[g * 4096 + k0 * 64 + h2]
                             : Wroot[g * 4096 + (k0 - 64) * 64 + h2];
        float w1 = (k1 < 64) ? Wrel[g * 4096 + k1 * 64 + h2]
                             : Wroot[g * 4096 + (k1 - 64) * 64 + h2];
        unsigned hi, lo;
        bf16split2(w0, w1, hi, lo);
        g_Wxp_hi[gid] = hi; g_Wxp_lo[gid] = lo;
    }
    if (gid < (KH / 2) * G4H) {
        int kp = gid >> 8, col = gid & 255;
        int g = col >> 6, h2 = col & 63;
        unsigned hi, lo;
        bf16split2(Wg[g * 4096 + (2 * kp) * 64 + h2],
                   Wg[g * 4096 + (2 * kp + 1) * 64 + h2], hi, lo);
        g_Wgp_hi[gid] = hi; g_Wgp_lo[gid] = lo;
    }
    if (gid < G4H) g_bc[gid] = brel[gid] + bg[gid];
}

// ---------------- main A2: agg_x gather, one warp per (node, t), 2-way unrolled ----------------
__global__ void k_xgather(const float* __restrict__ ea) {
    int node = (blockIdx.x * blockDim.x + threadIdx.x) >> 5;
    int t = blockIdx.y;
    int lane = threadIdx.x & 31;
    if (node >= NN) return;
    int beg = g_rowptr[node], end = g_rowptr[node + 1];
    const float* eat = ea + (long)t * EE;
    float* Xt = g_X + (long)t * NN * KX;
    float2 a0 = make_float2(0.f, 0.f);
    float2 a1 = make_float2(0.f, 0.f);
    int e = beg;
    for (; e + 2 <= end; e += 2) {
        int s0 = g_s_src[e], s1 = g_s_src[e + 1];
        float w0 = eat[g_s_eid[e]], w1 = eat[g_s_eid[e + 1]];
        float2 v0 = ((const float2*)(Xt + (long)s0 * KX + 64))[lane];
        float2 v1 = ((const float2*)(Xt + (long)s1 * KX + 64))[lane];
        a0.x += w0 * v0.x; a0.y += w0 * v0.y;
        a1.x += w1 * v1.x; a1.y += w1 * v1.y;
    }
    if (e < end) {
        int s0 = g_s_src[e];
        float w0 = eat[g_s_eid[e]];
        float2 v0 = ((const float2*)(Xt + (long)s0 * KX + 64))[lane];
        a0.x += w0 * v0.x; a0.y += w0 * v0.y;
    }
    a0.x += a1.x; a0.y += a1.y;
    ((float2*)(Xt + (long)node * KX))[lane] = a0;
}

// ---------------- main A3: big batched GEMM  P = X[80000,128] @ Wx[128,256] (3xBF16) ----------------
__global__ void __launch_bounds__(256) k_biggemm() {
    __shared__ unsigned Ah[64][12], Al[64][12];
    __shared__ unsigned Bh[8][264], Bl[8][264];
    int tid = threadIdx.x;
    int lane = tid & 31, warp = tid >> 5;
    int wm = warp >> 2, wn = warp & 3;
    int gq = lane >> 2, tg = lane & 3;
    long r0 = (long)blockIdx.x * 64;

    float acc[2][4][2][4];
#pragma unroll
    for (int a = 0; a < 2; a++)
#pragma unroll
        for (int b = 0; b < 4; b++)
#pragma unroll
            for (int cc = 0; cc < 2; cc++)
#pragma unroll
                for (int d = 0; d < 4; d++) acc[a][b][cc][d] = 0.f;

    int arow = tid >> 2;
    int ac4 = (tid & 3) * 4;
    int akp = (tid & 3) * 2;
    const float* Abase = g_X + (r0 + arow) * KX + ac4;

    for (int k0 = 0; k0 < KX; k0 += BK) {
        float4 av = *(const float4*)(Abase + k0);
        unsigned h0, l0, h1, l1;
        bf16split2(av.x, av.y, h0, l0);
        bf16split2(av.z, av.w, h1, l1);
        Ah[arow][akp] = h0; Ah[arow][akp + 1] = h1;
        Al[arow][akp] = l0; Al[arow][akp + 1] = l1;
        int kp0 = (k0 >> 1);
#pragma unroll
        for (int i = 0; i < 2; i++) {
            int flat4 = i * 256 + tid;
            int kpl = flat4 >> 6, c4 = (flat4 & 63) * 4;
            uint4 bh = *(const uint4*)(g_Wxp_hi + (kp0 + kpl) * G4H + c4);
            uint4 bl = *(const uint4*)(g_Wxp_lo + (kp0 + kpl) * G4H + c4);
            Bh[kpl][c4 + 0] = bh.x; Bh[kpl][c4 + 1] = bh.y;
            Bh[kpl][c4 + 2] = bh.z; Bh[kpl][c4 + 3] = bh.w;
            Bl[kpl][c4 + 0] = bl.x; Bl[kpl][c4 + 1] = bl.y;
            Bl[kpl][c4 + 2] = bl.z; Bl[kpl][c4 + 3] = bl.w;
        }
        __syncthreads();

        unsigned ahi[2][4], alo[2][4];
#pragma unroll
        for (int mi = 0; mi < 2; mi++) {
            int rb = wm * 32 + mi * 16;
            ahi[mi][0] = Ah[rb + gq][tg];     alo[mi][0] = Al[rb + gq][tg];
            ahi[mi][1] = Ah[rb + gq + 8][tg]; alo[mi][1] = Al[rb + gq + 8][tg];
            ahi[mi][2] = Ah[rb + gq][tg + 4]; alo[mi][2] = Al[rb + gq][tg + 4];
            ahi[mi][3] = Ah[rb + gq + 8][tg + 4]; alo[mi][3] = Al[rb + gq + 8][tg + 4];
        }
#pragma unroll
        for (int gg = 0; gg < 4; gg++)
#pragma unroll
            for (int s = 0; s < 2; s++) {
                int cb = gg * 64 + wn * 16 + s * 8 + gq;
                unsigned bh0 = Bh[tg][cb], bh1 = Bh[tg + 4][cb];
                unsigned bl0 = Bl[tg][cb], bl1 = Bl[tg + 4][cb];
#pragma unroll
                for (int mi = 0; mi < 2; mi++) {
                    float* C = acc[mi][gg][s];
                    MMA_BF16(C[0], C[1], C[2], C[3],
                             alo[mi][0], alo[mi][1], alo[mi][2], alo[mi][3], bh0, bh1);
                    MMA_BF16(C[0], C[1], C[2], C[3],
                             ahi[mi][0], ahi[mi][1], ahi[mi][2], ahi[mi][3], bl0, bl1);
                    MMA_BF16(C[0], C[1], C[2], C[3],
                             ahi[mi][0], ahi[mi][1], ahi[mi][2], ahi[mi][3], bh0, bh1);
                }
            }
        __syncthreads();
    }
#pragma unroll
    for (int mi = 0; mi < 2; mi++)
#pragma unroll
        for (int gg = 0; gg < 4; gg++)
#pragma unroll
            for (int s = 0; s < 2; s++)
#pragma unroll
                for (int half = 0; half < 2; half++) {
                    long row = r0 + wm * 32 + mi * 16 + gq + half * 8;
                    int j = gg * 64 + wn * 16 + s * 8 + tg * 2;
                    float2 v = make_float2(acc[mi][gg][s][half * 2 + 0],
                                           acc[mi][gg][s][half * 2 + 1]);
                    *(float2*)(g_P + row * G4H + j) = v;
                }
}

// ---------------- loop: gates = AH[NN,64]@Wg + P[t] + bc, fused cell (3xBF16) ----------------
__global__ void __launch_bounds__(256) k_hgemm(int t) {
    __shared__ unsigned Ah[64][12], Al[64][12];
    __shared__ unsigned Bh[8][264], Bl[8][264];
    __shared__ float sbc[256];
    int tid = threadIdx.x;
    int lane = tid & 31, warp = tid >> 5;
    int wm = warp >> 2, wn = warp & 3;
    int gq = lane >> 2, tg = lane & 3;
    int r0 = blockIdx.x * 64;
    sbc[tid] = g_bc[tid];

    float acc[2][4][2][4];
#pragma unroll
    for (int a = 0; a < 2; a++)
#pragma unroll
        for (int b = 0; b < 4; b++)
#pragma unroll
            for (int cc = 0; cc < 2; cc++)
#pragma unroll
                for (int d = 0; d < 4; d++) acc[a][b][cc][d] = 0.f;

    int arow = tid >> 2;
    int ac4 = (tid & 3) * 4;
    int akp = (tid & 3) * 2;
    bool rowok = (r0 + arow) < NN;
    const float* Abase = g_AH + (long)(r0 + arow) * KH + ac4;

    for (int k0 = 0; k0 < KH; k0 += BK) {
        float4 av = rowok ? *(const float4*)(Abase + k0) : make_float4(0.f, 0.f, 0.f, 0.f);
        unsigned h0, l0, h1, l1;
        bf16split2(av.x, av.y, h0, l0);
        bf16split2(av.z, av.w, h1, l1);
        Ah[arow][akp] = h0; Ah[arow][akp + 1] = h1;
        Al[arow][akp] = l0; Al[arow][akp + 1] = l1;
        int kp0 = (k0 >> 1);
#pragma unroll
        for (int i = 0; i < 2; i++) {
            int flat4 = i * 256 + tid;
            int kpl = flat4 >> 6, c4 = (flat4 & 63) * 4;
            uint4 bh = *(const uint4*)(g_Wgp_hi + (kp0 + kpl) * G4H + c4);
            uint4 bl = *(const uint4*)(g_Wgp_lo + (kp0 + kpl) * G4H + c4);
            Bh[kpl][c4 + 0] = bh.x; Bh[kpl][c4 + 1] = bh.y;
            Bh[kpl][c4 + 2] = bh.z; Bh[kpl][c4 + 3] = bh.w;
            Bl[kpl][c4 + 0] = bl.x; Bl[kpl][c4 + 1] = bl.y;
            Bl[kpl][c4 + 2] = bl.z; Bl[kpl][c4 + 3] = bl.w;
        }
        __syncthreads();

        unsigned ahi[2][4], alo[2][4];
#pragma unroll
        for (int mi = 0; mi < 2; mi++) {
            int rb = wm * 32 + mi * 16;
            ahi[mi][0] = Ah[rb + gq][tg];     alo[mi][0] = Al[rb + gq][tg];
            ahi[mi][1] = Ah[rb + gq + 8][tg]; alo[mi][1] = Al[rb + gq + 8][tg];
            ahi[mi][2] = Ah[rb + gq][tg + 4]; alo[mi][2] = Al[rb + gq][tg + 4];
            ahi[mi][3] = Ah[rb + gq + 8][tg + 4]; alo[mi][3] = Al[rb + gq + 8][tg + 4];
        }
#pragma unroll
        for (int gg = 0; gg < 4; gg++)
#pragma unroll
            for (int s = 0; s < 2; s++) {
                int cb = gg * 64 + wn * 16 + s * 8 + gq;
                unsigned bh0 = Bh[tg][cb], bh1 = Bh[tg + 4][cb];
                unsigned bl0 = Bl[tg][cb], bl1 = Bl[tg + 4][cb];
#pragma unroll
                for (int mi = 0; mi < 2; mi++) {
                    float* C = acc[mi][gg][s];
                    MMA_BF16(C[0], C[1], C[2], C[3],
                             alo[mi][0], alo[mi][1], alo[mi][2], alo[mi][3], bh0, bh1);
                    MMA_BF16(C[0], C[1], C[2], C[3],
                             ahi[mi][0], ahi[mi][1], ahi[mi][2], ahi[mi][3], bl0, bl1);
                    MMA_BF16(C[0], C[1], C[2], C[3],
                             ahi[mi][0], ahi[mi][1], ahi[mi][2], ahi[mi][3], bh0, bh1);
                }
            }
        __syncthreads();
    }

    // epilogue: + P[t] + bias, LSTM cell
#pragma unroll
    for (int mi = 0; mi < 2; mi++)
#pragma unroll
        for (int s = 0; s < 2; s++)
#pragma unroll
            for (int half = 0; half < 2; half++) {
                int row = r0 + wm * 32 + mi * 16 + gq + half * 8;
                if (row >= NN) continue;
                int j = wn * 16 + s * 8 + tg * 2;
                const float* Prow = g_P + ((long)t * NN + row) * G4H;
                float2 pi = *(const float2*)(Prow + j);
                float2 pf = *(const float2*)(Prow + 64 + j);
                float2 po = *(const float2*)(Prow + 128 + j);
                float2 pm = *(const float2*)(Prow + 192 + j);
                float2 cold = *(const float2*)(g_c + (long)row * 64 + j);
                float outc[2], outh[2];
#pragma unroll
                for (int cc = 0; cc < 2; cc++) {
                    int ri = half * 2 + cc;
                    float gi = acc[mi][0][s][ri] + (cc ? pi.y : pi.x) + sbc[j + cc];
                    float gf = acc[mi][1][s][ri] + (cc ? pf.y : pf.x) + sbc[64 + j + cc];
                    float go = acc[mi][2][s][ri] + (cc ? po.y : po.x) + sbc[128 + j + cc];
                    float gm = acc[mi][3][s][ri] + (cc ? pm.y : pm.x) + sbc[192 + j + cc];
                    float ii = sigm(gi), ff = sigm(gf), oo = sigm(go);
                    float mm = fmaxf(gm, 0.f);
                    float cv = tanhf(ii * mm + ff * (cc ? cold.y : cold.x));
                    outc[cc] = cv;
                    outh[cc] = oo * tanhf(cv);
                }
                *(float2*)(g_c + (long)row * 64 + j) = make_float2(outc[0], outc[1]);
                *(float2*)(g_h + (long)row * 64 + j) = make_float2(outh[0], outh[1]);
            }
}

// ---------------- DGPool ----------------
__global__ void k_vnorm(const float* __restrict__ pv) {
    __shared__ float red[64];
    int t = threadIdx.x;
    float v = pv[t];
    red[t] = v * v;
    __syncthreads();
    for (int s = 32; s > 0; s >>= 1) { if (t < s) red[t] += red[t + s]; __syncthreads(); }
    g_v[t] = v / (sqrtf(red[0]) + 1e-8f);
}

__global__ void k_scores() {
    __shared__ float ws[8];
    __shared__ int islast;
    int lane = threadIdx.x & 31, w = threadIdx.x >> 5;
    int n = blockIdx.x * 8 + w;
    float p = 0.f;
    if (n < NN)
        p = g_h[n * 64 + lane] * g_v[lane] + g_h[n * 64 + 32 + lane] * g_v[32 + lane];
    for (int o = 16; o; o >>= 1) p += __shfl_down_sync(0xffffffffu, p, o);
    if (lane == 0) {
        if (n < NN) g_raw[n] = p;
        ws[w] = (n < NN) ? p : 0.f;
    }
    __syncthreads();
    if (threadIdx.x == 0) {
        float s = 0.f, q = 0.f;
        for (int i = 0; i < 8; i++) { s += ws[i]; q += ws[i] * ws[i]; }
        atomicAdd(&g_ssum, s);
        atomicAdd(&g_ssq, q);
        __threadfence();
        islast = (atomicAdd(&g_sc_ticket, 1u) == gridDim.x - 1);
    }
    __syncthreads();
    if (islast && threadIdx.x == 0) {
        float fs = atomicAdd(&g_ssum, 0.f);
        float fq = atomicAdd(&g_ssq, 0.f);
        float mean = fs * (1.f / NN);
        float var = fq * (1.f / NN) - mean * mean;
        g_smean = mean;
        g_sinv = 1.f / (sqrtf(fmaxf(var, 0.f)) + 1e-8f);
        g_ssum = 0.f; g_ssq = 0.f; g_sc_ticket = 0u;
    }
}

__global__ void k_standardize(float* __restrict__ out) {
    int n = blockIdx.x * blockDim.x + threadIdx.x;
    float pl = 0.f;
    if (n < NN) {
        float s = (g_raw[n] - g_smean) * g_sinv;
        out[1 + n] = s;
        float sg = sigm(s);
        g_sig[n] = sg;
        unsigned u = __float_as_uint(s);
        u = (u & 0x80000000u) ? ~u : (u | 0x80000000u);
        g_key[n] = u;
        pl = sg * (1.f - sg);
    }
    for (int o = 16; o; o >>= 1) pl += __shfl_down_sync(0xffffffffu, pl, o);
    __shared__ float sred[8];
    if ((threadIdx.x & 31) == 0) sred[threadIdx.x >> 5] = pl;
    __syncthreads();
    if (threadIdx.x == 0) {
        float s = 0.f;
        for (int i = 0; i < 8; i++) s += sred[i];
        atomicAdd(&g_ploss, s);
    }
}

// single-block 4-pass radix select
__global__ void __launch_bounds__(1024) k_select() {
    __shared__ unsigned hist[256];
    __shared__ unsigned wsum[8];
    __shared__ unsigned s_prefix, s_kk;
    int t = threadIdx.x, lane = t & 31;
    if (t == 0) { s_prefix = 0u; s_kk = KSEL; }
#pragma unroll
    for (int pass = 0; pass < 4; pass++) {
        int shift = 24 - 8 * pass;
        if (t < 256) hist[t] = 0u;
        __syncthreads();
        unsigned pref = s_prefix;
        unsigned kk = s_kk;
        for (int i = t; i < NN; i += 1024) {
            unsigned k = g_key[i];
            bool cand = (pass == 0) || ((k >> (shift + 8)) == (pref >> (shift + 8)));
            if (cand) atomicAdd(&hist[(k >> shift) & 255u], 1u);
        }
        __syncthreads();
        unsigned x = 0, v = 0;
        if (t < 256) {
            int b = 255 - t;
            v = hist[b];
            x = v;
#pragma unroll
            for (int o = 1; o < 32; o <<= 1) {
                unsigned y = __shfl_up_sync(0xffffffffu, x, o);
                if (lane >= o) x += y;
            }
            if (lane == 31) wsum[t >> 5] = x;
        }
        __syncthreads();
        if (t < 256) {
            unsigned add = 0;
            int w = t >> 5;
            for (int j = 0; j < w; j++) add += wsum[j];
            unsigned S = x + add;
            unsigned Snext = S - v;
            if (S >= kk && Snext < kk) {
                s_prefix = pref | ((unsigned)(255 - t) << shift);
                s_kk = kk - Snext;
            }
        }
        __syncthreads();
    }
    if (t == 0) { g_prefix = s_prefix; g_kkleft = s_kk; }
}

__global__ void k_sumhigh() {
    __shared__ float acc[64];
    if (threadIdx.x < 64) acc[threadIdx.x] = 0.f;
    __syncthreads();
    int lane = threadIdx.x & 31, w = threadIdx.x >> 5;
    int n = blockIdx.x * 8 + w;
    if (n < NN) {
        int inc = 0;
        if (lane == 0) {
            unsigned key = g_key[n], tau = g_prefix;
            if (key > tau) inc = 1;
            else if (key == tau) {
                unsigned tk = atomicAdd(&g_ticket, 1u);
                inc = (tk < g_kkleft) ? 1 : 0;
            }
        }
        inc = __shfl_sync(0xffffffffu, inc, 0);
        if (inc) {
            float sg = g_sig[n];
            atomicAdd(&acc[lane],      g_h[n * 64 + lane] * sg);
            atomicAdd(&acc[lane + 32], g_h[n * 64 + lane + 32] * sg);
        }
    }
    __syncthreads();
    if (threadIdx.x < 64) atomicAdd(&g_high[threadIdx.x], acc[threadIdx.x]);
}

// ---------------- branch C: raw-fMRI LSTM ----------------
__global__ void k_Ggemm(const float* __restrict__ Wih, const float* __restrict__ ts) {
    __shared__ float sW[32][65];
    __shared__ float sT[32][51];
    int r0 = blockIdx.y * 64;
    int kbeg = blockIdx.x * KCH;
    int kend = min(NN, kbeg + KCH);
    int tid = threadIdx.x;
    int r = tid & 63, tq = tid >> 6;
    float acc[13];
#pragma unroll
    for (int j = 0; j < 13; j++) acc[j] = 0.f;

    for (int k0 = kbeg; k0 < kend; k0 += 32) {
#pragma unroll
        for (int i = 0; i < 8; i++) {
            int flat = i * 256 + tid;
            int kk = flat & 31, rr = flat >> 5;
            int kg = k0 + kk;
            sW[kk][rr] = (kg < kend) ? Wih[(long)(r0 + rr) * NN + kg] : 0.f;
        }
#pragma unroll
        for (int i = 0; i < 7; i++) {
            int flat = i * 256 + tid;
            if (flat < 1600) {
                int kk = flat & 31, t = flat >> 5;
                int kg = k0 + kk;
                sT[kk][t] = (kg < kend) ? ts[(long)t * NN + kg] : 0.f;
            }
        }
        __syncthreads();
#pragma unroll
        for (int kk = 0; kk < 32; kk++) {
            float wv = sW[kk][r];
#pragma unroll
            for (int j = 0; j < 13; j++) {
                int t = tq + 4 * j;
                if (t < TSN) acc[j] += wv * sT[kk][t];
            }
        }
        __syncthreads();
    }
#pragma unroll
    for (int j = 0; j < 13; j++) {
        int t = tq + 4 * j;
        if (t < TSN) atomicAdd(&g_G[t * G4H + r0 + r], acc[j]);
    }
}

__global__ void k_lstm(const float* __restrict__ Whh, const float* __restrict__ bih,
                       const float* __restrict__ bhh) {
    __shared__ float sh[64], scc[64], sg[256];
    int r = threadIdx.x;
    float wr[64];
#pragma unroll
    for (int m = 0; m < 64; m++) wr[m] = Whh[r * 64 + m];
    float bias = bih[r] + bhh[r];
    if (r < 64) { sh[r] = 0.f; scc[r] = 0.f; }
    __syncthreads();
    for (int t = 0; t < TSN; t++) {
        float a0 = 0.f, a1 = 0.f, a2 = 0.f, a3 = 0.f;
#pragma unroll
        for (int m = 0; m < 64; m += 4) {
            a0 += wr[m] * sh[m];
            a1 += wr[m + 1] * sh[m + 1];
            a2 += wr[m + 2] * sh[m + 2];
            a3 += wr[m + 3] * sh[m + 3];
        }
        float gv = g_G[t * G4H + r];
        g_G[t * G4H + r] = 0.f;   // reset for next replay
        sg[r] = gv + bias + ((a0 + a1) + (a2 + a3));
        __syncthreads();
        if (r < 64) {
            float gi = sg[r], gf = sg[64 + r], gg = sg[128 + r], go = sg[192 + r];
            float c = sigm(gf) * scc[r] + sigm(gi) * tanhf(gg);
            scc[r] = c;
            sh[r] = sigm(go) * tanhf(c);
        }
        __syncthreads();
    }
    if (r < 64) g_hl[r] = sh[r];
}

// ---------------- fusion head (+global resets for next replay) ----------------
__global__ void k_final(const float* __restrict__ lng, const float* __restrict__ lnb,
                        const float* __restrict__ W1, const float* __restrict__ b1,
                        const float* __restrict__ W2, const float* __restrict__ b2,
                        float* __restrict__ out) {
    __shared__ float red[128], sf[128], sz[64];
    int tid = threadIdx.x;
    float x = (tid < 64) ? g_high[tid] * (1.f / KSEL) : g_hl[tid - 64];
    if (tid < 64) g_high[tid] = 0.f;
    red[tid] = x;
    __syncthreads();
    for (int s = 64; s > 0; s >>= 1) { if (tid < s) red[tid] += red[tid + s]; __syncthreads(); }
    float mean = red[0] * (1.f / 128.f);
    __syncthreads();
    float d = x - mean;
    red[tid] = d * d;
    __syncthreads();
    for (int s = 64; s > 0; s >>= 1) { if (tid < s) red[tid] += red[tid + s]; __syncthreads(); }
    float var = red[0] * (1.f / 128.f);
    float y = d * rsqrtf(var + 1e-5f) * lng[tid] + lnb[tid];
    __syncthreads();
    sf[tid] = y;
    __syncthreads();
    if (tid < 64) {
        float a = b1[tid];
        for (int j = 0; j < 128; j++) a += sf[j] * W1[j * 64 + tid];
        sz[tid] = fmaxf(a, 0.f);
    }
    __syncthreads();
    red[tid] = (tid < 64) ? sz[tid] * W2[tid] : 0.f;
    __syncthreads();
    for (int s = 64; s > 0; s >>= 1) { if (tid < s) red[tid] += red[tid + s]; __syncthreads(); }
    if (tid == 0) {
        out[0] = red[0] + b2[0];
        out[NN + 1] = g_ploss * (1.f / NN);
        g_ploss = 0.f;
        g_ticket = 0u;
    }
}

// ---------------- launch (forked graph; streams/events created ONCE) ----------------
extern "C" void kernel_launch(void* const* d_in, const int* in_sizes, int n_in,
                              void* d_out, int out_size) {
    const float* xs   = (const float*)d_in[0];
    const void*  ei   = d_in[1];
    const float* ea   = (const float*)d_in[2];
    const float* h0   = (const float*)d_in[3];
    const float* c0   = (const float*)d_in[4];
    const float* ts   = (const float*)d_in[5];
    const float* Wrel = (const float*)d_in[6];
    const float* brel = (const float*)d_in[7];
    const float* Wroot= (const float*)d_in[8];
    const float* Wg   = (const float*)d_in[9];
    const float* bg   = (const float*)d_in[10];
    const float* pool = (const float*)d_in[11];
    const float* lng  = (const float*)d_in[12];
    const float* lnb  = (const float*)d_in[13];
    const float* Wih  = (const float*)d_in[14];
    const float* Whh  = (const float*)d_in[15];
    const float* bih  = (const float*)d_in[16];
    const float* bhh  = (const float*)d_in[17];
    const float* W1   = (const float*)d_in[18];
    const float* b1   = (const float*)d_in[19];
    const float* W2   = (const float*)d_in[20];
    const float* b2   = (const float*)d_in[21];
    float* out = (float*)d_out;

    static cudaStream_t sB = nullptr, sC = nullptr;
    static cudaEvent_t evFork = nullptr, evEdges = nullptr, evLstm = nullptr,
                       evV = nullptr, evAH0 = nullptr;
    if (sB == nullptr) {
        cudaStreamCreateWithFlags(&sB, cudaStreamNonBlocking);
        cudaStreamCreateWithFlags(&sC, cudaStreamNonBlocking);
        cudaEventCreateWithFlags(&evFork, cudaEventDisableTiming);
        cudaEventCreateWithFlags(&evEdges, cudaEventDisableTiming);
        cudaEventCreateWithFlags(&evLstm, cudaEventDisableTiming);
        cudaEventCreateWithFlags(&evV, cudaEventDisableTiming);
        cudaEventCreateWithFlags(&evAH0, cudaEventDisableTiming);
    }

    cudaEventRecord(evFork, 0);
    cudaStreamWaitEvent(sB, evFork, 0);
    cudaStreamWaitEvent(sC, evFork, 0);

    // branch B: edge structure + h/c init + t=0 agg_h gather (overlaps main prologue)
    k_decode<<<EE / 256, 256, 0, sB>>>(ei, h0, c0);
    k_prefix<<<1, 1024, 0, sB>>>();
    k_sortedges<<<EE / 256, 256, 0, sB>>>();
    cudaEventRecord(evEdges, sB);
    k_hgather<<<(NN * 32 + 255) / 256, 256, 0, sB>>>();
    cudaEventRecord(evAH0, sB);

    // branch C: pool-vec norm + fMRI LSTM (independent of main until scores/final)
    k_vnorm<<<1, 64, 0, sC>>>(pool);
    cudaEventRecord(evV, sC);
    k_Ggemm<<<dim3(128, 4), 256, 0, sC>>>(Wih, ts);
    k_lstm<<<1, 256, 0, sC>>>(Whh, bih, bhh);
    cudaEventRecord(evLstm, sC);

    // main branch
    k_colstats<<<dim3(40, TT), 256>>>(xs);
    k_prep<<<(TT * NN * FF) / 256, 256>>>(xs, Wrel, brel, Wroot, Wg, bg);
    cudaStreamWaitEvent(0, evEdges, 0);
    k_xgather<<<dim3((NN * 32 + 255) / 256, TT), 256>>>(ea);
    k_biggemm<<<(TT * NN) / 64, 256>>>();

    cudaStreamWaitEvent(0, evAH0, 0);
    k_hgemm<<<(NN + 63) / 64, 256>>>(0);   // t=0 AH pre-gathered on branch B
    for (int t = 1; t < TT; t++) {
        k_hgather<<<(NN * 32 + 255) / 256, 256>>>();
        k_hgemm<<<(NN + 63) / 64, 256>>>(t);
    }

    cudaStreamWaitEvent(0, evV, 0);
    k_scores<<<(NN + 7) / 8, 256>>>();
    k_standardize<<<(NN + 255) / 256, 256>>>(out);
    k_select<<<1, 1024>>>();
    k_sumhigh<<<(NN + 7) / 8, 256>>>();

    cudaStreamWaitEvent(0, evLstm, 0);
    k_final<<<1, 128>>>(lng, lnb, W1, b1, W2, b2, out);
}

// round 15
// speedup vs baseline: 1.0516x; 1.0516x over previous
#include <cuda_runtime.h>
#include <cuda_bf16.h>
#include <stdint.h>

#define TT   4
#define NN   20000
#define EE   320000
#define FF   64
#define HH   64
#define TSN  50
#define G4H  256
#define KX   128     // aggx(64) | xn(64)
#define KH   64      // aggh
#define KSEL 10000
#define BK   16
#define KCH  157     // Ggemm K-chunk: 128 splits * 157 >= 20000
#define NB0  313     // biggemm blocks covering t=0 rows (0..20031)
#define NBALL 1250   // total biggemm blocks (TT*NN/64)

// ---------------- device scratch (zero-initialized at load) ----------------
__device__ __align__(16) float g_X[(long)TT * NN * KX];
__device__ __align__(16) float g_P[(long)TT * NN * G4H];
__device__ __align__(16) float g_AH[NN * KH];
__device__ __align__(16) float g_h[NN * HH];
__device__ __align__(16) float g_c[NN * HH];
__device__ float g_dinv[NN];
__device__ float g_self[NN];
__device__ __align__(16) int g_cnt[NN];
__device__ int   g_cursor[NN];
__device__ int   g_rowptr[NN + 1];
__device__ int   g_src[EE];
__device__ int   g_dst[EE];
__device__ int   g_s_src[EE];
__device__ int   g_s_eid[EE];
__device__ float g_s_gcn[EE];
__device__ __align__(16) unsigned g_Wxp_hi[(KX / 2) * G4H];
__device__ __align__(16) unsigned g_Wxp_lo[(KX / 2) * G4H];
__device__ __align__(16) unsigned g_Wgp_hi[(KH / 2) * G4H];
__device__ __align__(16) unsigned g_Wgp_lo[(KH / 2) * G4H];
__device__ __align__(16) float g_bc[G4H];
__device__ float g_colsum[TT * FF];
__device__ float g_colsq[TT * FF];
__device__ float g_mean[TT * FF];
__device__ float g_rinv[TT * FF];
__device__ float g_v[HH];
__device__ float g_raw[NN];
__device__ float g_sig[NN];
__device__ unsigned g_key[NN];
__device__ float g_high[HH];
__device__ __align__(16) float g_G[TSN * G4H];
__device__ float g_hl[HH];
__device__ unsigned g_prefix;
__device__ unsigned g_kkleft;
__device__ unsigned g_ticket;
__device__ unsigned g_cs_ticket[TT];
__device__ unsigned g_sc_ticket;
__device__ float g_ssum, g_ssq, g_smean, g_sinv, g_ploss;

__device__ __forceinline__ float sigm(float x) { return 1.f / (1.f + expf(-x)); }

// split (a,b) into packed bf16x2 hi + lo (2-term bf16 split; drops only lo*lo ~2^-18)
__device__ __forceinline__ void bf16split2(float a, float b, unsigned& hi, unsigned& lo) {
    __nv_bfloat16 ah = __float2bfloat16_rn(a);
    __nv_bfloat16 bh = __float2bfloat16_rn(b);
    float ar = a - __bfloat162float(ah);
    float br = b - __bfloat162float(bh);
    __nv_bfloat162 H; H.x = ah; H.y = bh;
    __nv_bfloat162 L; L.x = __float2bfloat16_rn(ar); L.y = __float2bfloat16_rn(br);
    hi = *(unsigned*)&H;
    lo = *(unsigned*)&L;
}

#define MMA_BF16(c0, c1, c2, c3, a0, a1, a2, a3, b0, b1)                         \
    asm volatile("mma.sync.aligned.m16n8k16.row.col.f32.bf16.bf16.f32 "          \
                 "{%0,%1,%2,%3}, {%4,%5,%6,%7}, {%8,%9}, {%0,%1,%2,%3};"         \
                 : "+f"(c0), "+f"(c1), "+f"(c2), "+f"(c3)                        \
                 : "r"(a0), "r"(a1), "r"(a2), "r"(a3), "r"(b0), "r"(b1))

// ---------------- branch B0: decode edges (+count) + copy h0/c0 ----------------
__global__ void k_decode(const void* eiraw, const float* __restrict__ h0,
                         const float* __restrict__ c0) {
    int gid = blockIdx.x * blockDim.x + threadIdx.x;   // exactly EE threads
    const long long* p64 = (const long long*)eiraw;
    bool is64 = true;
#pragma unroll
    for (int j = 0; j < 8; j++) {
        long long v = p64[j];
        if (v < 0 || v >= NN) is64 = false;
    }
    int s, d;
    if (is64) { s = (int)p64[gid]; d = (int)p64[EE + gid]; }
    else { const int* p32 = (const int*)eiraw; s = p32[gid]; d = p32[EE + gid]; }
    s = min(max(s, 0), NN - 1);
    d = min(max(d, 0), NN - 1);
    g_src[gid] = s;
    g_dst[gid] = d;
    atomicAdd(&g_cnt[d], 1);
    for (int j = gid; j < NN * HH; j += EE) { g_h[j] = h0[j]; g_c[j] = c0[j]; }
}

// ---------------- branch B1: fast single-block prefix scan + node norms ----------------
__global__ void k_prefix() {
    __shared__ int wsum[32];
    int t = threadIdx.x, lane = t & 31, wid = t >> 5;
    int vals[20];
    int s = 0;
    if (t < 1000) {
        const int4* p = (const int4*)(g_cnt + t * 20);
#pragma unroll
        for (int i = 0; i < 5; i++) {
            int4 v = p[i];
            vals[i * 4 + 0] = v.x; vals[i * 4 + 1] = v.y;
            vals[i * 4 + 2] = v.z; vals[i * 4 + 3] = v.w;
            s += v.x + v.y + v.z + v.w;
        }
    }
    int x = s;
#pragma unroll
    for (int o = 1; o < 32; o <<= 1) {
        int y = __shfl_up_sync(0xffffffffu, x, o);
        if (lane >= o) x += y;
    }
    if (lane == 31) wsum[wid] = x;
    __syncthreads();
    if (wid == 0) {
        int sv = wsum[lane];
#pragma unroll
        for (int o = 1; o < 32; o <<= 1) {
            int y = __shfl_up_sync(0xffffffffu, sv, o);
            if (lane >= o) sv += y;
        }
        wsum[lane] = sv;
    }
    __syncthreads();
    int excl = x - s + (wid > 0 ? wsum[wid - 1] : 0);
    if (t < 1000) {
        int run = excl;
#pragma unroll
        for (int j = 0; j < 20; j++) {
            int idx = t * 20 + j;
            g_rowptr[idx] = run;
            int v = vals[j];
            run += v;
            float dd = (float)v + 1.f;
            g_dinv[idx] = rsqrtf(dd);
            g_self[idx] = 1.f / dd;
            g_cnt[idx] = 0;   // reset for next replay
        }
    }
    if (t == 1023) g_rowptr[NN] = excl;
}

// ---------------- branch B2: bucket edges by destination ----------------
__global__ void k_sortedges() {
    int e = blockIdx.x * blockDim.x + threadIdx.x;
    if (e >= EE) return;
    int s = g_src[e], d = g_dst[e];
    int pos = g_rowptr[d] + atomicAdd(&g_cursor[d], 1);
    g_s_src[pos] = s;
    g_s_eid[pos] = e;
    g_s_gcn[pos] = g_dinv[s] * g_dinv[d];
}

// ---------------- agg_h gather (one warp per node) ----------------
__global__ void k_hgather() {
    int node = (blockIdx.x * blockDim.x + threadIdx.x) >> 5;
    int lane = threadIdx.x & 31;
    if (node >= NN) return;
    if (lane == 0) g_cursor[node] = 0;   // idempotent reset for next replay
    int beg = g_rowptr[node], end = g_rowptr[node + 1];
    float slf = g_self[node];
    float2 hv = ((const float2*)(g_h + (long)node * 64))[lane];
    float2 acc = make_float2(slf * hv.x, slf * hv.y);
    for (int e = beg; e < end; e++) {
        int s = g_s_src[e];
        float gn = g_s_gcn[e];
        float2 v = ((const float2*)(g_h + (long)s * 64))[lane];
        acc.x += gn * v.x;
        acc.y += gn * v.y;
    }
    ((float2*)(g_AH + (long)node * 64))[lane] = acc;
}

// ---------------- main A0: per-timestep column stats ----------------
__global__ void k_colstats(const float* __restrict__ xs) {
    __shared__ float ss[256], sq[256];
    __shared__ int islast;
    int t = blockIdx.y;
    const float* xt = xs + (long)t * NN * FF;
    int f = threadIdx.x & 63, slot = threadIdx.x >> 6;
    float s = 0.f, q = 0.f;
    for (int n = blockIdx.x * 4 + slot; n < NN; n += gridDim.x * 4) {
        float v = xt[n * 64 + f];
        s += v; q += v * v;
    }
    ss[threadIdx.x] = s; sq[threadIdx.x] = q;
    __syncthreads();
    if (slot == 0) {
        s = ss[f] + ss[f + 64] + ss[f + 128] + ss[f + 192];
        q = sq[f] + sq[f + 64] + sq[f + 128] + sq[f + 192];
        atomicAdd(&g_colsum[t * 64 + f], s);
        atomicAdd(&g_colsq[t * 64 + f], q);
    }
    __syncthreads();
    if (threadIdx.x == 0) {
        __threadfence();
        islast = (atomicAdd(&g_cs_ticket[t], 1u) == gridDim.x - 1);
    }
    __syncthreads();
    if (islast && threadIdx.x < 64) {
        int o = t * 64 + threadIdx.x;
        float fs = atomicAdd(&g_colsum[o], 0.f);
        float fq = atomicAdd(&g_colsq[o], 0.f);
        float mean = fs * (1.f / NN);
        float var = (fq - fs * fs * (1.f / NN)) * (1.f / (NN - 1));
        g_mean[o] = mean;
        g_rinv[o] = 1.f / (sqrtf(fmaxf(var, 0.f)) + 1e-6f);
        g_colsum[o] = 0.f;
        g_colsq[o] = 0.f;
        if (threadIdx.x == 0) g_cs_ticket[t] = 0u;
    }
}

// ---------------- main A1: normalize x (all T) + pack/split weights ----------------
__global__ void k_prep(const float* __restrict__ xs,
                       const float* __restrict__ Wrel, const float* __restrict__ brel,
                       const float* __restrict__ Wroot, const float* __restrict__ Wg,
                       const float* __restrict__ bg) {
    int gid = blockIdx.x * blockDim.x + threadIdx.x;   // TT*NN*FF threads
    int t = gid / (NN * FF);
    int rem = gid - t * (NN * FF);
    int n = rem >> 6, f = rem & 63;
    float xn = (xs[gid] - g_mean[t * 64 + f]) * g_rinv[t * 64 + f];
    g_X[((long)t * NN + n) * KX + 64 + f] = xn;

    if (gid < (KX / 2) * G4H) {
        int kp = gid >> 8, col = gid & 255;
        int g = col >> 6, h2 = col & 63;
        int k0 = 2 * kp, k1 = 2 * kp + 1;
        float w0 = (k0 < 64) ? Wrel[g * 4096 + k0 * 64 + h2]
                             : Wroot[g * 4096 + (k0 - 64) * 64 + h2];
        float w1 = (k1 < 64) ? Wrel[g * 4096 + k1 * 64 + h2]
                             : Wroot[g * 4096 + (k1 - 64) * 64 + h2];
        unsigned hi, lo;
        bf16split2(w0, w1, hi, lo);
        g_Wxp_hi[gid] = hi; g_Wxp_lo[gid] = lo;
    }
    if (gid < (KH / 2) * G4H) {
        int kp = gid >> 8, col = gid & 255;
        int g = col >> 6, h2 = col & 63;
        unsigned hi, lo;
        bf16split2(Wg[g * 4096 + (2 * kp) * 64 + h2],
                   Wg[g * 4096 + (2 * kp + 1) * 64 + h2], hi, lo);
        g_Wgp_hi[gid] = hi; g_Wgp_lo[gid] = lo;
    }
    if (gid < G4H) g_bc[gid] = brel[gid] + bg[gid];
}

// ---------------- main A2: agg_x gather, one warp per (node, t) ----------------
__global__ void k_xgather(const float* __restrict__ ea) {
    int node = (blockIdx.x * blockDim.x + threadIdx.x) >> 5;
    int t = blockIdx.y;
    int lane = threadIdx.x & 31;
    if (node >= NN) return;
    int beg = g_rowptr[node], end = g_rowptr[node + 1];
    const float* eat = ea + (long)t * EE;
    float* Xt = g_X + (long)t * NN * KX;
    float2 acc = make_float2(0.f, 0.f);
    for (int e = beg; e < end; e++) {
        int s = g_s_src[e];
        float w = eat[g_s_eid[e]];
        float2 v = ((const float2*)(Xt + (long)s * KX + 64))[lane];
        acc.x += w * v.x;
        acc.y += w * v.y;
    }
    ((float2*)(Xt + (long)node * KX))[lane] = acc;
}

// ---------------- main A3: big batched GEMM  P = X[80000,128] @ Wx[128,256] (3xBF16)
// Launched in two parts via blk0 offset so hgemm(0) can start after part 0.
__global__ void __launch_bounds__(256) k_biggemm(int blk0) {
    __shared__ unsigned Ah[64][12], Al[64][12];
    __shared__ unsigned Bh[8][264], Bl[8][264];
    int tid = threadIdx.x;
    int lane = tid & 31, warp = tid >> 5;
    int wm = warp >> 2, wn = warp & 3;
    int gq = lane >> 2, tg = lane & 3;
    long r0 = (long)(blk0 + blockIdx.x) * 64;

    float acc[2][4][2][4];
#pragma unroll
    for (int a = 0; a < 2; a++)
#pragma unroll
        for (int b = 0; b < 4; b++)
#pragma unroll
            for (int cc = 0; cc < 2; cc++)
#pragma unroll
                for (int d = 0; d < 4; d++) acc[a][b][cc][d] = 0.f;

    int arow = tid >> 2;
    int ac4 = (tid & 3) * 4;
    int akp = (tid & 3) * 2;
    const float* Abase = g_X + (r0 + arow) * KX + ac4;

    for (int k0 = 0; k0 < KX; k0 += BK) {
        float4 av = *(const float4*)(Abase + k0);
        unsigned h0, l0, h1, l1;
        bf16split2(av.x, av.y, h0, l0);
        bf16split2(av.z, av.w, h1, l1);
        Ah[arow][akp] = h0; Ah[arow][akp + 1] = h1;
        Al[arow][akp] = l0; Al[arow][akp + 1] = l1;
        int kp0 = (k0 >> 1);
#pragma unroll
        for (int i = 0; i < 2; i++) {
            int flat4 = i * 256 + tid;
            int kpl = flat4 >> 6, c4 = (flat4 & 63) * 4;
            uint4 bh = *(const uint4*)(g_Wxp_hi + (kp0 + kpl) * G4H + c4);
            uint4 bl = *(const uint4*)(g_Wxp_lo + (kp0 + kpl) * G4H + c4);
            Bh[kpl][c4 + 0] = bh.x; Bh[kpl][c4 + 1] = bh.y;
            Bh[kpl][c4 + 2] = bh.z; Bh[kpl][c4 + 3] = bh.w;
            Bl[kpl][c4 + 0] = bl.x; Bl[kpl][c4 + 1] = bl.y;
            Bl[kpl][c4 + 2] = bl.z; Bl[kpl][c4 + 3] = bl.w;
        }
        __syncthreads();

        unsigned ahi[2][4], alo[2][4];
#pragma unroll
        for (int mi = 0; mi < 2; mi++) {
            int rb = wm * 32 + mi * 16;
            ahi[mi][0] = Ah[rb + gq][tg];     alo[mi][0] = Al[rb + gq][tg];
            ahi[mi][1] = Ah[rb + gq + 8][tg]; alo[mi][1] = Al[rb + gq + 8][tg];
            ahi[mi][2] = Ah[rb + gq][tg + 4]; alo[mi][2] = Al[rb + gq][tg + 4];
            ahi[mi][3] = Ah[rb + gq + 8][tg + 4]; alo[mi][3] = Al[rb + gq + 8][tg + 4];
        }
#pragma unroll
        for (int gg = 0; gg < 4; gg++)
#pragma unroll
            for (int s = 0; s < 2; s++) {
                int cb = gg * 64 + wn * 16 + s * 8 + gq;
                unsigned bh0 = Bh[tg][cb], bh1 = Bh[tg + 4][cb];
                unsigned bl0 = Bl[tg][cb], bl1 = Bl[tg + 4][cb];
#pragma unroll
                for (int mi = 0; mi < 2; mi++) {
                    float* C = acc[mi][gg][s];
                    MMA_BF16(C[0], C[1], C[2], C[3],
                             alo[mi][0], alo[mi][1], alo[mi][2], alo[mi][3], bh0, bh1);
                    MMA_BF16(C[0], C[1], C[2], C[3],
                             ahi[mi][0], ahi[mi][1], ahi[mi][2], ahi[mi][3], bl0, bl1);
                    MMA_BF16(C[0], C[1], C[2], C[3],
                             ahi[mi][0], ahi[mi][1], ahi[mi][2], ahi[mi][3], bh0, bh1);
                }
            }
        __syncthreads();
    }
#pragma unroll
    for (int mi = 0; mi < 2; mi++)
#pragma unroll
        for (int gg = 0; gg < 4; gg++)
#pragma unroll
            for (int s = 0; s < 2; s++)
#pragma unroll
                for (int half = 0; half < 2; half++) {
                    long row = r0 + wm * 32 + mi * 16 + gq + half * 8;
                    int j = gg * 64 + wn * 16 + s * 8 + tg * 2;
                    float2 v = make_float2(acc[mi][gg][s][half * 2 + 0],
                                           acc[mi][gg][s][half * 2 + 1]);
                    *(float2*)(g_P + row * G4H + j) = v;
                }
}

// ---------------- loop: gates = AH[NN,64]@Wg + P[t] + bc, fused cell (3xBF16) ----------------
__global__ void __launch_bounds__(256) k_hgemm(int t) {
    __shared__ unsigned Ah[64][12], Al[64][12];
    __shared__ unsigned Bh[8][264], Bl[8][264];
    __shared__ float sbc[256];
    int tid = threadIdx.x;
    int lane = tid & 31, warp = tid >> 5;
    int wm = warp >> 2, wn = warp & 3;
    int gq = lane >> 2, tg = lane & 3;
    int r0 = blockIdx.x * 64;
    sbc[tid] = g_bc[tid];

    float acc[2][4][2][4];
#pragma unroll
    for (int a = 0; a < 2; a++)
#pragma unroll
        for (int b = 0; b < 4; b++)
#pragma unroll
            for (int cc = 0; cc < 2; cc++)
#pragma unroll
                for (int d = 0; d < 4; d++) acc[a][b][cc][d] = 0.f;

    int arow = tid >> 2;
    int ac4 = (tid & 3) * 4;
    int akp = (tid & 3) * 2;
    bool rowok = (r0 + arow) < NN;
    const float* Abase = g_AH + (long)(r0 + arow) * KH + ac4;

    for (int k0 = 0; k0 < KH; k0 += BK) {
        float4 av = rowok ? *(const float4*)(Abase + k0) : make_float4(0.f, 0.f, 0.f, 0.f);
        unsigned h0, l0, h1, l1;
        bf16split2(av.x, av.y, h0, l0);
        bf16split2(av.z, av.w, h1, l1);
        Ah[arow][akp] = h0; Ah[arow][akp + 1] = h1;
        Al[arow][akp] = l0; Al[arow][akp + 1] = l1;
        int kp0 = (k0 >> 1);
#pragma unroll
        for (int i = 0; i < 2; i++) {
            int flat4 = i * 256 + tid;
            int kpl = flat4 >> 6, c4 = (flat4 & 63) * 4;
            uint4 bh = *(const uint4*)(g_Wgp_hi + (kp0 + kpl) * G4H + c4);
            uint4 bl = *(const uint4*)(g_Wgp_lo + (kp0 + kpl) * G4H + c4);
            Bh[kpl][c4 + 0] = bh.x; Bh[kpl][c4 + 1] = bh.y;
            Bh[kpl][c4 + 2] = bh.z; Bh[kpl][c4 + 3] = bh.w;
            Bl[kpl][c4 + 0] = bl.x; Bl[kpl][c4 + 1] = bl.y;
            Bl[kpl][c4 + 2] = bl.z; Bl[kpl][c4 + 3] = bl.w;
        }
        __syncthreads();

        unsigned ahi[2][4], alo[2][4];
#pragma unroll
        for (int mi = 0; mi < 2; mi++) {
            int rb = wm * 32 + mi * 16;
            ahi[mi][0] = Ah[rb + gq][tg];     alo[mi][0] = Al[rb + gq][tg];
            ahi[mi][1] = Ah[rb + gq + 8][tg]; alo[mi][1] = Al[rb + gq + 8][tg];
            ahi[mi][2] = Ah[rb + gq][tg + 4]; alo[mi][2] = Al[rb + gq][tg + 4];
            ahi[mi][3] = Ah[rb + gq + 8][tg + 4]; alo[mi][3] = Al[rb + gq + 8][tg + 4];
        }
#pragma unroll
        for (int gg = 0; gg < 4; gg++)
#pragma unroll
            for (int s = 0; s < 2; s++) {
                int cb = gg * 64 + wn * 16 + s * 8 + gq;
                unsigned bh0 = Bh[tg][cb], bh1 = Bh[tg + 4][cb];
                unsigned bl0 = Bl[tg][cb], bl1 = Bl[tg + 4][cb];
#pragma unroll
                for (int mi = 0; mi < 2; mi++) {
                    float* C = acc[mi][gg][s];
                    MMA_BF16(C[0], C[1], C[2], C[3],
                             alo[mi][0], alo[mi][1], alo[mi][2], alo[mi][3], bh0, bh1);
                    MMA_BF16(C[0], C[1], C[2], C[3],
                             ahi[mi][0], ahi[mi][1], ahi[mi][2], ahi[mi][3], bl0, bl1);
                    MMA_BF16(C[0], C[1], C[2], C[3],
                             ahi[mi][0], ahi[mi][1], ahi[mi][2], ahi[mi][3], bh0, bh1);
                }
            }
        __syncthreads();
    }

    // epilogue: + P[t] + bias, LSTM cell
#pragma unroll
    for (int mi = 0; mi < 2; mi++)
#pragma unroll
        for (int s = 0; s < 2; s++)
#pragma unroll
            for (int half = 0; half < 2; half++) {
                int row = r0 + wm * 32 + mi * 16 + gq + half * 8;
                if (row >= NN) continue;
                int j = wn * 16 + s * 8 + tg * 2;
                const float* Prow = g_P + ((long)t * NN + row) * G4H;
                float2 pi = *(const float2*)(Prow + j);
                float2 pf = *(const float2*)(Prow + 64 + j);
                float2 po = *(const float2*)(Prow + 128 + j);
                float2 pm = *(const float2*)(Prow + 192 + j);
                float2 cold = *(const float2*)(g_c + (long)row * 64 + j);
                float outc[2], outh[2];
#pragma unroll
                for (int cc = 0; cc < 2; cc++) {
                    int ri = half * 2 + cc;
                    float gi = acc[mi][0][s][ri] + (cc ? pi.y : pi.x) + sbc[j + cc];
                    float gf = acc[mi][1][s][ri] + (cc ? pf.y : pf.x) + sbc[64 + j + cc];
                    float go = acc[mi][2][s][ri] + (cc ? po.y : po.x) + sbc[128 + j + cc];
                    float gm = acc[mi][3][s][ri] + (cc ? pm.y : pm.x) + sbc[192 + j + cc];
                    float ii = sigm(gi), ff = sigm(gf), oo = sigm(go);
                    float mm = fmaxf(gm, 0.f);
                    float cv = tanhf(ii * mm + ff * (cc ? cold.y : cold.x));
                    outc[cc] = cv;
                    outh[cc] = oo * tanhf(cv);
                }
                *(float2*)(g_c + (long)row * 64 + j) = make_float2(outc[0], outc[1]);
                *(float2*)(g_h + (long)row * 64 + j) = make_float2(outh[0], outh[1]);
            }
}

// ---------------- DGPool ----------------
__global__ void k_vnorm(const float* __restrict__ pv) {
    __shared__ float red[64];
    int t = threadIdx.x;
    float v = pv[t];
    red[t] = v * v;
    __syncthreads();
    for (int s = 32; s > 0; s >>= 1) { if (t < s) red[t] += red[t + s]; __syncthreads(); }
    g_v[t] = v / (sqrtf(red[0]) + 1e-8f);
}

__global__ void k_scores() {
    __shared__ float ws[8];
    __shared__ int islast;
    int lane = threadIdx.x & 31, w = threadIdx.x >> 5;
    int n = blockIdx.x * 8 + w;
    float p = 0.f;
    if (n < NN)
        p = g_h[n * 64 + lane] * g_v[lane] + g_h[n * 64 + 32 + lane] * g_v[32 + lane];
    for (int o = 16; o; o >>= 1) p += __shfl_down_sync(0xffffffffu, p, o);
    if (lane == 0) {
        if (n < NN) g_raw[n] = p;
        ws[w] = (n < NN) ? p : 0.f;
    }
    __syncthreads();
    if (threadIdx.x == 0) {
        float s = 0.f, q = 0.f;
        for (int i = 0; i < 8; i++) { s += ws[i]; q += ws[i] * ws[i]; }
        atomicAdd(&g_ssum, s);
        atomicAdd(&g_ssq, q);
        __threadfence();
        islast = (atomicAdd(&g_sc_ticket, 1u) == gridDim.x - 1);
    }
    __syncthreads();
    if (islast && threadIdx.x == 0) {
        float fs = atomicAdd(&g_ssum, 0.f);
        float fq = atomicAdd(&g_ssq, 0.f);
        float mean = fs * (1.f / NN);
        float var = fq * (1.f / NN) - mean * mean;
        g_smean = mean;
        g_sinv = 1.f / (sqrtf(fmaxf(var, 0.f)) + 1e-8f);
        g_ssum = 0.f; g_ssq = 0.f; g_sc_ticket = 0u;
    }
}

__global__ void k_standardize(float* __restrict__ out) {
    int n = blockIdx.x * blockDim.x + threadIdx.x;
    float pl = 0.f;
    if (n < NN) {
        float s = (g_raw[n] - g_smean) * g_sinv;
        out[1 + n] = s;
        float sg = sigm(s);
        g_sig[n] = sg;
        unsigned u = __float_as_uint(s);
        u = (u & 0x80000000u) ? ~u : (u | 0x80000000u);
        g_key[n] = u;
        pl = sg * (1.f - sg);
    }
    for (int o = 16; o; o >>= 1) pl += __shfl_down_sync(0xffffffffu, pl, o);
    __shared__ float sred[8];
    if ((threadIdx.x & 31) == 0) sred[threadIdx.x >> 5] = pl;
    __syncthreads();
    if (threadIdx.x == 0) {
        float s = 0.f;
        for (int i = 0; i < 8; i++) s += sred[i];
        atomicAdd(&g_ploss, s);
    }
}

// single-block 4-pass radix select
__global__ void __launch_bounds__(1024) k_select() {
    __shared__ unsigned hist[256];
    __shared__ unsigned wsum[8];
    __shared__ unsigned s_prefix, s_kk;
    int t = threadIdx.x, lane = t & 31;
    if (t == 0) { s_prefix = 0u; s_kk = KSEL; }
#pragma unroll
    for (int pass = 0; pass < 4; pass++) {
        int shift = 24 - 8 * pass;
        if (t < 256) hist[t] = 0u;
        __syncthreads();
        unsigned pref = s_prefix;
        unsigned kk = s_kk;
        for (int i = t; i < NN; i += 1024) {
            unsigned k = g_key[i];
            bool cand = (pass == 0) || ((k >> (shift + 8)) == (pref >> (shift + 8)));
            if (cand) atomicAdd(&hist[(k >> shift) & 255u], 1u);
        }
        __syncthreads();
        unsigned x = 0, v = 0;
        if (t < 256) {
            int b = 255 - t;
            v = hist[b];
            x = v;
#pragma unroll
            for (int o = 1; o < 32; o <<= 1) {
                unsigned y = __shfl_up_sync(0xffffffffu, x, o);
                if (lane >= o) x += y;
            }
            if (lane == 31) wsum[t >> 5] = x;
        }
        __syncthreads();
        if (t < 256) {
            unsigned add = 0;
            int w = t >> 5;
            for (int j = 0; j < w; j++) add += wsum[j];
            unsigned S = x + add;
            unsigned Snext = S - v;
            if (S >= kk && Snext < kk) {
                s_prefix = pref | ((unsigned)(255 - t) << shift);
                s_kk = kk - Snext;
            }
        }
        __syncthreads();
    }
    if (t == 0) { g_prefix = s_prefix; g_kkleft = s_kk; }
}

__global__ void k_sumhigh() {
    __shared__ float acc[64];
    if (threadIdx.x < 64) acc[threadIdx.x] = 0.f;
    __syncthreads();
    int lane = threadIdx.x & 31, w = threadIdx.x >> 5;
    int n = blockIdx.x * 8 + w;
    if (n < NN) {
        int inc = 0;
        if (lane == 0) {
            unsigned key = g_key[n], tau = g_prefix;
            if (key > tau) inc = 1;
            else if (key == tau) {
                unsigned tk = atomicAdd(&g_ticket, 1u);
                inc = (tk < g_kkleft) ? 1 : 0;
            }
        }
        inc = __shfl_sync(0xffffffffu, inc, 0);
        if (inc) {
            float sg = g_sig[n];
            atomicAdd(&acc[lane],      g_h[n * 64 + lane] * sg);
            atomicAdd(&acc[lane + 32], g_h[n * 64 + lane + 32] * sg);
        }
    }
    __syncthreads();
    if (threadIdx.x < 64) atomicAdd(&g_high[threadIdx.x], acc[threadIdx.x]);
}

// ---------------- branch C: raw-fMRI LSTM ----------------
__global__ void k_Ggemm(const float* __restrict__ Wih, const float* __restrict__ ts) {
    __shared__ float sW[32][65];
    __shared__ float sT[32][51];
    int r0 = blockIdx.y * 64;
    int kbeg = blockIdx.x * KCH;
    int kend = min(NN, kbeg + KCH);
    int tid = threadIdx.x;
    int r = tid & 63, tq = tid >> 6;
    float acc[13];
#pragma unroll
    for (int j = 0; j < 13; j++) acc[j] = 0.f;

    for (int k0 = kbeg; k0 < kend; k0 += 32) {
#pragma unroll
        for (int i = 0; i < 8; i++) {
            int flat = i * 256 + tid;
            int kk = flat & 31, rr = flat >> 5;
            int kg = k0 + kk;
            sW[kk][rr] = (kg < kend) ? Wih[(long)(r0 + rr) * NN + kg] : 0.f;
        }
#pragma unroll
        for (int i = 0; i < 7; i++) {
            int flat = i * 256 + tid;
            if (flat < 1600) {
                int kk = flat & 31, t = flat >> 5;
                int kg = k0 + kk;
                sT[kk][t] = (kg < kend) ? ts[(long)t * NN + kg] : 0.f;
            }
        }
        __syncthreads();
#pragma unroll
        for (int kk = 0; kk < 32; kk++) {
            float wv = sW[kk][r];
#pragma unroll
            for (int j = 0; j < 13; j++) {
                int t = tq + 4 * j;
                if (t < TSN) acc[j] += wv * sT[kk][t];
            }
        }
        __syncthreads();
    }
#pragma unroll
    for (int j = 0; j < 13; j++) {
        int t = tq + 4 * j;
        if (t < TSN) atomicAdd(&g_G[t * G4H + r0 + r], acc[j]);
    }
}

__global__ void k_lstm(const float* __restrict__ Whh, const float* __restrict__ bih,
                       const float* __restrict__ bhh) {
    __shared__ float sh[64], scc[64], sg[256];
    int r = threadIdx.x;
    float wr[64];
#pragma unroll
    for (int m = 0; m < 64; m++) wr[m] = Whh[r * 64 + m];
    float bias = bih[r] + bhh[r];
    if (r < 64) { sh[r] = 0.f; scc[r] = 0.f; }
    __syncthreads();
    for (int t = 0; t < TSN; t++) {
        float a0 = 0.f, a1 = 0.f, a2 = 0.f, a3 = 0.f;
#pragma unroll
        for (int m = 0; m < 64; m += 4) {
            a0 += wr[m] * sh[m];
            a1 += wr[m + 1] * sh[m + 1];
            a2 += wr[m + 2] * sh[m + 2];
            a3 += wr[m + 3] * sh[m + 3];
        }
        float gv = g_G[t * G4H + r];
        g_G[t * G4H + r] = 0.f;   // reset for next replay
        sg[r] = gv + bias + ((a0 + a1) + (a2 + a3));
        __syncthreads();
        if (r < 64) {
            float gi = sg[r], gf = sg[64 + r], gg = sg[128 + r], go = sg[192 + r];
            float c = sigm(gf) * scc[r] + sigm(gi) * tanhf(gg);
            scc[r] = c;
            sh[r] = sigm(go) * tanhf(c);
        }
        __syncthreads();
    }
    if (r < 64) g_hl[r] = sh[r];
}

// ---------------- fusion head (+global resets for next replay) ----------------
__global__ void k_final(const float* __restrict__ lng, const float* __restrict__ lnb,
                        const float* __restrict__ W1, const float* __restrict__ b1,
                        const float* __restrict__ W2, const float* __restrict__ b2,
                        float* __restrict__ out) {
    __shared__ float red[128], sf[128], sz[64];
    int tid = threadIdx.x;
    float x = (tid < 64) ? g_high[tid] * (1.f / KSEL) : g_hl[tid - 64];
    if (tid < 64) g_high[tid] = 0.f;
    red[tid] = x;
    __syncthreads();
    for (int s = 64; s > 0; s >>= 1) { if (tid < s) red[tid] += red[tid + s]; __syncthreads(); }
    float mean = red[0] * (1.f / 128.f);
    __syncthreads();
    float d = x - mean;
    red[tid] = d * d;
    __syncthreads();
    for (int s = 64; s > 0; s >>= 1) { if (tid < s) red[tid] += red[tid + s]; __syncthreads(); }
    float var = red[0] * (1.f / 128.f);
    float y = d * rsqrtf(var + 1e-5f) * lng[tid] + lnb[tid];
    __syncthreads();
    sf[tid] = y;
    __syncthreads();
    if (tid < 64) {
        float a = b1[tid];
        for (int j = 0; j < 128; j++) a += sf[j] * W1[j * 64 + tid];
        sz[tid] = fmaxf(a, 0.f);
    }
    __syncthreads();
    red[tid] = (tid < 64) ? sz[tid] * W2[tid] : 0.f;
    __syncthreads();
    for (int s = 64; s > 0; s >>= 1) { if (tid < s) red[tid] += red[tid + s]; __syncthreads(); }
    if (tid == 0) {
        out[0] = red[0] + b2[0];
        out[NN + 1] = g_ploss * (1.f / NN);
        g_ploss = 0.f;
        g_ticket = 0u;
    }
}

// ---------------- launch (forked graph; streams/events created ONCE) ----------------
extern "C" void kernel_launch(void* const* d_in, const int* in_sizes, int n_in,
                              void* d_out, int out_size) {
    const float* xs   = (const float*)d_in[0];
    const void*  ei   = d_in[1];
    const float* ea   = (const float*)d_in[2];
    const float* h0   = (const float*)d_in[3];
    const float* c0   = (const float*)d_in[4];
    const float* ts   = (const float*)d_in[5];
    const float* Wrel = (const float*)d_in[6];
    const float* brel = (const float*)d_in[7];
    const float* Wroot= (const float*)d_in[8];
    const float* Wg   = (const float*)d_in[9];
    const float* bg   = (const float*)d_in[10];
    const float* pool = (const float*)d_in[11];
    const float* lng  = (const float*)d_in[12];
    const float* lnb  = (const float*)d_in[13];
    const float* Wih  = (const float*)d_in[14];
    const float* Whh  = (const float*)d_in[15];
    const float* bih  = (const float*)d_in[16];
    const float* bhh  = (const float*)d_in[17];
    const float* W1   = (const float*)d_in[18];
    const float* b1   = (const float*)d_in[19];
    const float* W2   = (const float*)d_in[20];
    const float* b2   = (const float*)d_in[21];
    float* out = (float*)d_out;

    static cudaStream_t sB = nullptr, sC = nullptr;
    static cudaEvent_t evFork = nullptr, evEdges = nullptr, evLstm = nullptr,
                       evV = nullptr, evAH0 = nullptr, evXG = nullptr, evPrest = nullptr;
    if (sB == nullptr) {
        cudaStreamCreateWithFlags(&sB, cudaStreamNonBlocking);
        cudaStreamCreateWithFlags(&sC, cudaStreamNonBlocking);
        cudaEventCreateWithFlags(&evFork, cudaEventDisableTiming);
        cudaEventCreateWithFlags(&evEdges, cudaEventDisableTiming);
        cudaEventCreateWithFlags(&evLstm, cudaEventDisableTiming);
        cudaEventCreateWithFlags(&evV, cudaEventDisableTiming);
        cudaEventCreateWithFlags(&evAH0, cudaEventDisableTiming);
        cudaEventCreateWithFlags(&evXG, cudaEventDisableTiming);
        cudaEventCreateWithFlags(&evPrest, cudaEventDisableTiming);
    }

    cudaEventRecord(evFork, 0);
    cudaStreamWaitEvent(sB, evFork, 0);
    cudaStreamWaitEvent(sC, evFork, 0);

    // branch B: edge structure + h/c init + t=0 agg_h gather (overlaps main prologue)
    k_decode<<<EE / 256, 256, 0, sB>>>(ei, h0, c0);
    k_prefix<<<1, 1024, 0, sB>>>();
    k_sortedges<<<EE / 256, 256, 0, sB>>>();
    cudaEventRecord(evEdges, sB);
    k_hgather<<<(NN * 32 + 255) / 256, 256, 0, sB>>>();
    cudaEventRecord(evAH0, sB);

    // branch C: pool-vec norm + fMRI LSTM (independent of main until scores/final)
    k_vnorm<<<1, 64, 0, sC>>>(pool);
    cudaEventRecord(evV, sC);
    k_Ggemm<<<dim3(128, 4), 256, 0, sC>>>(Wih, ts);
    k_lstm<<<1, 256, 0, sC>>>(Whh, bih, bhh);
    cudaEventRecord(evLstm, sC);

    // main branch
    k_colstats<<<dim3(40, TT), 256>>>(xs);
    k_prep<<<(TT * NN * FF) / 256, 256>>>(xs, Wrel, brel, Wroot, Wg, bg);
    cudaStreamWaitEvent(0, evEdges, 0);
    k_xgather<<<dim3((NN * 32 + 255) / 256, TT), 256>>>(ea);
    cudaEventRecord(evXG, 0);

    // biggemm split: t=0 rows on main; remainder on branch B concurrent with hgemm(0)
    k_biggemm<<<NB0, 256>>>(0);
    cudaStreamWaitEvent(sB, evXG, 0);
    k_biggemm<<<NBALL - NB0, 256, 0, sB>>>(NB0);
    cudaEventRecord(evPrest, sB);

    cudaStreamWaitEvent(0, evAH0, 0);
    k_hgemm<<<(NN + 63) / 64, 256>>>(0);   // t=0 AH pre-gathered on branch B
    k_hgather<<<(NN * 32 + 255) / 256, 256>>>();
    cudaStreamWaitEvent(0, evPrest, 0);
    k_hgemm<<<(NN + 63) / 64, 256>>>(1);
    for (int t = 2; t < TT; t++) {
        k_hgather<<<(NN * 32 + 255) / 256, 256>>>();
        k_hgemm<<<(NN + 63) / 64, 256>>>(t);
    }

    cudaStreamWaitEvent(0, evV, 0);
    k_scores<<<(NN + 7) / 8, 256>>>();
    k_standardize<<<(NN + 255) / 256, 256>>>(out);
    k_select<<<1, 1024>>>();
    k_sumhigh<<<(NN + 7) / 8, 256>>>();

    cudaStreamWaitEvent(0, evLstm, 0);
    k_final<<<1, 128>>>(lng, lnb, W1, b1, W2, b2, out);
}

// round 16
// speedup vs baseline: 1.0912x; 1.0376x over previous
#include <cuda_runtime.h>
#include <cuda_bf16.h>
#include <stdint.h>

#define TT   4
#define NN   20000
#define EE   320000
#define FF   64
#define HH   64
#define TSN  50
#define G4H  256
#define KX   128     // aggx(64) | xn(64)
#define KH   64      // aggh
#define KSEL 10000
#define BK   16
#define KCH  157     // Ggemm K-chunk: 128 splits * 157 >= 20000
#define NBALL 1250   // total biggemm blocks (TT*NN/64)
// chunk boundaries: hgemm(t) needs P rows [t*NN,(t+1)*NN) -> blocks [ceil-ish]
#define CB0  313     // blocks [0,313)    rows 0..20031     (covers t=0)
#define CB1  625     // blocks [313,625)  rows 20032..40031 (covers t=1 w/ chunk0)
#define CB2  938     // blocks [625,938)  rows 40032..60031 (covers t=2 w/ prior)
                     // blocks [938,1250) rows 60032..79999 (covers t=3 w/ prior)

// ---------------- device scratch (zero-initialized at load) ----------------
__device__ __align__(16) float g_X[(long)TT * NN * KX];
__device__ __align__(16) float g_P[(long)TT * NN * G4H];
__device__ __align__(16) float g_AH[NN * KH];
__device__ __align__(16) float g_h[NN * HH];
__device__ __align__(16) float g_c[NN * HH];
__device__ float g_dinv[NN];
__device__ float g_self[NN];
__device__ __align__(16) int g_cnt[NN];
__device__ int   g_cursor[NN];
__device__ int   g_rowptr[NN + 1];
__device__ int   g_src[EE];
__device__ int   g_dst[EE];
__device__ int   g_s_src[EE];
__device__ int   g_s_eid[EE];
__device__ float g_s_gcn[EE];
__device__ __align__(16) unsigned g_Wxp_hi[(KX / 2) * G4H];
__device__ __align__(16) unsigned g_Wxp_lo[(KX / 2) * G4H];
__device__ __align__(16) unsigned g_Wgp_hi[(KH / 2) * G4H];
__device__ __align__(16) unsigned g_Wgp_lo[(KH / 2) * G4H];
__device__ __align__(16) float g_bc[G4H];
__device__ float g_colsum[TT * FF];
__device__ float g_colsq[TT * FF];
__device__ float g_mean[TT * FF];
__device__ float g_rinv[TT * FF];
__device__ float g_v[HH];
__device__ float g_raw[NN];
__device__ float g_sig[NN];
__device__ unsigned g_key[NN];
__device__ float g_high[HH];
__device__ __align__(16) float g_G[TSN * G4H];
__device__ float g_hl[HH];
__device__ unsigned g_prefix;
__device__ unsigned g_kkleft;
__device__ unsigned g_ticket;
__device__ unsigned g_cs_ticket[TT];
__device__ unsigned g_sc_ticket;
__device__ float g_ssum, g_ssq, g_smean, g_sinv, g_ploss;

__device__ __forceinline__ float sigm(float x) { return 1.f / (1.f + expf(-x)); }

// split (a,b) into packed bf16x2 hi + lo (2-term bf16 split; drops only lo*lo ~2^-18)
__device__ __forceinline__ void bf16split2(float a, float b, unsigned& hi, unsigned& lo) {
    __nv_bfloat16 ah = __float2bfloat16_rn(a);
    __nv_bfloat16 bh = __float2bfloat16_rn(b);
    float ar = a - __bfloat162float(ah);
    float br = b - __bfloat162float(bh);
    __nv_bfloat162 H; H.x = ah; H.y = bh;
    __nv_bfloat162 L; L.x = __float2bfloat16_rn(ar); L.y = __float2bfloat16_rn(br);
    hi = *(unsigned*)&H;
    lo = *(unsigned*)&L;
}

#define MMA_BF16(c0, c1, c2, c3, a0, a1, a2, a3, b0, b1)                         \
    asm volatile("mma.sync.aligned.m16n8k16.row.col.f32.bf16.bf16.f32 "          \
                 "{%0,%1,%2,%3}, {%4,%5,%6,%7}, {%8,%9}, {%0,%1,%2,%3};"         \
                 : "+f"(c0), "+f"(c1), "+f"(c2), "+f"(c3)                        \
                 : "r"(a0), "r"(a1), "r"(a2), "r"(a3), "r"(b0), "r"(b1))

// ---------------- branch B0: decode edges (+count) + copy h0/c0 ----------------
__global__ void k_decode(const void* eiraw, const float* __restrict__ h0,
                         const float* __restrict__ c0) {
    int gid = blockIdx.x * blockDim.x + threadIdx.x;   // exactly EE threads
    const long long* p64 = (const long long*)eiraw;
    bool is64 = true;
#pragma unroll
    for (int j = 0; j < 8; j++) {
        long long v = p64[j];
        if (v < 0 || v >= NN) is64 = false;
    }
    int s, d;
    if (is64) { s = (int)p64[gid]; d = (int)p64[EE + gid]; }
    else { const int* p32 = (const int*)eiraw; s = p32[gid]; d = p32[EE + gid]; }
    s = min(max(s, 0), NN - 1);
    d = min(max(d, 0), NN - 1);
    g_src[gid] = s;
    g_dst[gid] = d;
    atomicAdd(&g_cnt[d], 1);
    for (int j = gid; j < NN * HH; j += EE) { g_h[j] = h0[j]; g_c[j] = c0[j]; }
}

// ---------------- branch B1: fast single-block prefix scan + node norms ----------------
__global__ void k_prefix() {
    __shared__ int wsum[32];
    int t = threadIdx.x, lane = t & 31, wid = t >> 5;
    int vals[20];
    int s = 0;
    if (t < 1000) {
        const int4* p = (const int4*)(g_cnt + t * 20);
#pragma unroll
        for (int i = 0; i < 5; i++) {
            int4 v = p[i];
            vals[i * 4 + 0] = v.x; vals[i * 4 + 1] = v.y;
            vals[i * 4 + 2] = v.z; vals[i * 4 + 3] = v.w;
            s += v.x + v.y + v.z + v.w;
        }
    }
    int x = s;
#pragma unroll
    for (int o = 1; o < 32; o <<= 1) {
        int y = __shfl_up_sync(0xffffffffu, x, o);
        if (lane >= o) x += y;
    }
    if (lane == 31) wsum[wid] = x;
    __syncthreads();
    if (wid == 0) {
        int sv = wsum[lane];
#pragma unroll
        for (int o = 1; o < 32; o <<= 1) {
            int y = __shfl_up_sync(0xffffffffu, sv, o);
            if (lane >= o) sv += y;
        }
        wsum[lane] = sv;
    }
    __syncthreads();
    int excl = x - s + (wid > 0 ? wsum[wid - 1] : 0);
    if (t < 1000) {
        int run = excl;
#pragma unroll
        for (int j = 0; j < 20; j++) {
            int idx = t * 20 + j;
            g_rowptr[idx] = run;
            int v = vals[j];
            run += v;
            float dd = (float)v + 1.f;
            g_dinv[idx] = rsqrtf(dd);
            g_self[idx] = 1.f / dd;
            g_cnt[idx] = 0;   // reset for next replay
        }
    }
    if (t == 1023) g_rowptr[NN] = excl;
}

// ---------------- branch B2: bucket edges by destination ----------------
__global__ void k_sortedges() {
    int e = blockIdx.x * blockDim.x + threadIdx.x;
    if (e >= EE) return;
    int s = g_src[e], d = g_dst[e];
    int pos = g_rowptr[d] + atomicAdd(&g_cursor[d], 1);
    g_s_src[pos] = s;
    g_s_eid[pos] = e;
    g_s_gcn[pos] = g_dinv[s] * g_dinv[d];
}

// ---------------- agg_h gather (one warp per node) ----------------
__global__ void k_hgather() {
    int node = (blockIdx.x * blockDim.x + threadIdx.x) >> 5;
    int lane = threadIdx.x & 31;
    if (node >= NN) return;
    if (lane == 0) g_cursor[node] = 0;   // idempotent reset for next replay
    int beg = g_rowptr[node], end = g_rowptr[node + 1];
    float slf = g_self[node];
    float2 hv = ((const float2*)(g_h + (long)node * 64))[lane];
    float2 acc = make_float2(slf * hv.x, slf * hv.y);
    for (int e = beg; e < end; e++) {
        int s = g_s_src[e];
        float gn = g_s_gcn[e];
        float2 v = ((const float2*)(g_h + (long)s * 64))[lane];
        acc.x += gn * v.x;
        acc.y += gn * v.y;
    }
    ((float2*)(g_AH + (long)node * 64))[lane] = acc;
}

// ---------------- main A0: per-timestep column stats ----------------
__global__ void k_colstats(const float* __restrict__ xs) {
    __shared__ float ss[256], sq[256];
    __shared__ int islast;
    int t = blockIdx.y;
    const float* xt = xs + (long)t * NN * FF;
    int f = threadIdx.x & 63, slot = threadIdx.x >> 6;
    float s = 0.f, q = 0.f;
    for (int n = blockIdx.x * 4 + slot; n < NN; n += gridDim.x * 4) {
        float v = xt[n * 64 + f];
        s += v; q += v * v;
    }
    ss[threadIdx.x] = s; sq[threadIdx.x] = q;
    __syncthreads();
    if (slot == 0) {
        s = ss[f] + ss[f + 64] + ss[f + 128] + ss[f + 192];
        q = sq[f] + sq[f + 64] + sq[f + 128] + sq[f + 192];
        atomicAdd(&g_colsum[t * 64 + f], s);
        atomicAdd(&g_colsq[t * 64 + f], q);
    }
    __syncthreads();
    if (threadIdx.x == 0) {
        __threadfence();
        islast = (atomicAdd(&g_cs_ticket[t], 1u) == gridDim.x - 1);
    }
    __syncthreads();
    if (islast && threadIdx.x < 64) {
        int o = t * 64 + threadIdx.x;
        float fs = atomicAdd(&g_colsum[o], 0.f);
        float fq = atomicAdd(&g_colsq[o], 0.f);
        float mean = fs * (1.f / NN);
        float var = (fq - fs * fs * (1.f / NN)) * (1.f / (NN - 1));
        g_mean[o] = mean;
        g_rinv[o] = 1.f / (sqrtf(fmaxf(var, 0.f)) + 1e-6f);
        g_colsum[o] = 0.f;
        g_colsq[o] = 0.f;
        if (threadIdx.x == 0) g_cs_ticket[t] = 0u;
    }
}

// ---------------- main A1: normalize x (all T) + pack/split weights ----------------
__global__ void k_prep(const float* __restrict__ xs,
                       const float* __restrict__ Wrel, const float* __restrict__ brel,
                       const float* __restrict__ Wroot, const float* __restrict__ Wg,
                       const float* __restrict__ bg) {
    int gid = blockIdx.x * blockDim.x + threadIdx.x;   // TT*NN*FF threads
    int t = gid / (NN * FF);
    int rem = gid - t * (NN * FF);
    int n = rem >> 6, f = rem & 63;
    float xn = (xs[gid] - g_mean[t * 64 + f]) * g_rinv[t * 64 + f];
    g_X[((long)t * NN + n) * KX + 64 + f] = xn;

    if (gid < (KX / 2) * G4H) {
        int kp = gid >> 8, col = gid & 255;
        int g = col >> 6, h2 = col & 63;
        int k0 = 2 * kp, k1 = 2 * kp + 1;
        float w0 = (k0 < 64) ? Wrel[g * 4096 + k0 * 64 + h2]
                             : Wroot[g * 4096 + (k0 - 64) * 64 + h2];
        float w1 = (k1 < 64) ? Wrel[g * 4096 + k1 * 64 + h2]
                             : Wroot[g * 4096 + (k1 - 64) * 64 + h2];
        unsigned hi, lo;
        bf16split2(w0, w1, hi, lo);
        g_Wxp_hi[gid] = hi; g_Wxp_lo[gid] = lo;
    }
    if (gid < (KH / 2) * G4H) {
        int kp = gid >> 8, col = gid & 255;
        int g = col >> 6, h2 = col & 63;
        unsigned hi, lo;
        bf16split2(Wg[g * 4096 + (2 * kp) * 64 + h2],
                   Wg[g * 4096 + (2 * kp + 1) * 64 + h2], hi, lo);
        g_Wgp_hi[gid] = hi; g_Wgp_lo[gid] = lo;
    }
    if (gid < G4H) g_bc[gid] = brel[gid] + bg[gid];
}

// ---------------- main A2: agg_x gather, one warp per (node, t) ----------------
__global__ void k_xgather(const float* __restrict__ ea) {
    int node = (blockIdx.x * blockDim.x + threadIdx.x) >> 5;
    int t = blockIdx.y;
    int lane = threadIdx.x & 31;
    if (node >= NN) return;
    int beg = g_rowptr[node], end = g_rowptr[node + 1];
    const float* eat = ea + (long)t * EE;
    float* Xt = g_X + (long)t * NN * KX;
    float2 acc = make_float2(0.f, 0.f);
    for (int e = beg; e < end; e++) {
        int s = g_s_src[e];
        float w = eat[g_s_eid[e]];
        float2 v = ((const float2*)(Xt + (long)s * KX + 64))[lane];
        acc.x += w * v.x;
        acc.y += w * v.y;
    }
    ((float2*)(Xt + (long)node * KX))[lane] = acc;
}

// ---------------- main A3: big batched GEMM  P = X[80000,128] @ Wx[128,256] (3xBF16)
// Launched in chunks via blk0 offset for fine-grained overlap with the h-loop.
__global__ void __launch_bounds__(256) k_biggemm(int blk0) {
    __shared__ unsigned Ah[64][12], Al[64][12];
    __shared__ unsigned Bh[8][264], Bl[8][264];
    int tid = threadIdx.x;
    int lane = tid & 31, warp = tid >> 5;
    int wm = warp >> 2, wn = warp & 3;
    int gq = lane >> 2, tg = lane & 3;
    long r0 = (long)(blk0 + blockIdx.x) * 64;

    float acc[2][4][2][4];
#pragma unroll
    for (int a = 0; a < 2; a++)
#pragma unroll
        for (int b = 0; b < 4; b++)
#pragma unroll
            for (int cc = 0; cc < 2; cc++)
#pragma unroll
                for (int d = 0; d < 4; d++) acc[a][b][cc][d] = 0.f;

    int arow = tid >> 2;
    int ac4 = (tid & 3) * 4;
    int akp = (tid & 3) * 2;
    const float* Abase = g_X + (r0 + arow) * KX + ac4;

    for (int k0 = 0; k0 < KX; k0 += BK) {
        float4 av = *(const float4*)(Abase + k0);
        unsigned h0, l0, h1, l1;
        bf16split2(av.x, av.y, h0, l0);
        bf16split2(av.z, av.w, h1, l1);
        Ah[arow][akp] = h0; Ah[arow][akp + 1] = h1;
        Al[arow][akp] = l0; Al[arow][akp + 1] = l1;
        int kp0 = (k0 >> 1);
#pragma unroll
        for (int i = 0; i < 2; i++) {
            int flat4 = i * 256 + tid;
            int kpl = flat4 >> 6, c4 = (flat4 & 63) * 4;
            uint4 bh = *(const uint4*)(g_Wxp_hi + (kp0 + kpl) * G4H + c4);
            uint4 bl = *(const uint4*)(g_Wxp_lo + (kp0 + kpl) * G4H + c4);
            Bh[kpl][c4 + 0] = bh.x; Bh[kpl][c4 + 1] = bh.y;
            Bh[kpl][c4 + 2] = bh.z; Bh[kpl][c4 + 3] = bh.w;
            Bl[kpl][c4 + 0] = bl.x; Bl[kpl][c4 + 1] = bl.y;
            Bl[kpl][c4 + 2] = bl.z; Bl[kpl][c4 + 3] = bl.w;
        }
        __syncthreads();

        unsigned ahi[2][4], alo[2][4];
#pragma unroll
        for (int mi = 0; mi < 2; mi++) {
            int rb = wm * 32 + mi * 16;
            ahi[mi][0] = Ah[rb + gq][tg];     alo[mi][0] = Al[rb + gq][tg];
            ahi[mi][1] = Ah[rb + gq + 8][tg]; alo[mi][1] = Al[rb + gq + 8][tg];
            ahi[mi][2] = Ah[rb + gq][tg + 4]; alo[mi][2] = Al[rb + gq][tg + 4];
            ahi[mi][3] = Ah[rb + gq + 8][tg + 4]; alo[mi][3] = Al[rb + gq + 8][tg + 4];
        }
#pragma unroll
        for (int gg = 0; gg < 4; gg++)
#pragma unroll
            for (int s = 0; s < 2; s++) {
                int cb = gg * 64 + wn * 16 + s * 8 + gq;
                unsigned bh0 = Bh[tg][cb], bh1 = Bh[tg + 4][cb];
                unsigned bl0 = Bl[tg][cb], bl1 = Bl[tg + 4][cb];
#pragma unroll
                for (int mi = 0; mi < 2; mi++) {
                    float* C = acc[mi][gg][s];
                    MMA_BF16(C[0], C[1], C[2], C[3],
                             alo[mi][0], alo[mi][1], alo[mi][2], alo[mi][3], bh0, bh1);
                    MMA_BF16(C[0], C[1], C[2], C[3],
                             ahi[mi][0], ahi[mi][1], ahi[mi][2], ahi[mi][3], bl0, bl1);
                    MMA_BF16(C[0], C[1], C[2], C[3],
                             ahi[mi][0], ahi[mi][1], ahi[mi][2], ahi[mi][3], bh0, bh1);
                }
            }
        __syncthreads();
    }
#pragma unroll
    for (int mi = 0; mi < 2; mi++)
#pragma unroll
        for (int gg = 0; gg < 4; gg++)
#pragma unroll
            for (int s = 0; s < 2; s++)
#pragma unroll
                for (int half = 0; half < 2; half++) {
                    long row = r0 + wm * 32 + mi * 16 + gq + half * 8;
                    int j = gg * 64 + wn * 16 + s * 8 + tg * 2;
                    float2 v = make_float2(acc[mi][gg][s][half * 2 + 0],
                                           acc[mi][gg][s][half * 2 + 1]);
                    *(float2*)(g_P + row * G4H + j) = v;
                }
}

// ---------------- loop: gates = AH[NN,64]@Wg + P[t] + bc, fused cell (3xBF16) ----------------
__global__ void __launch_bounds__(256) k_hgemm(int t) {
    __shared__ unsigned Ah[64][12], Al[64][12];
    __shared__ unsigned Bh[8][264], Bl[8][264];
    __shared__ float sbc[256];
    int tid = threadIdx.x;
    int lane = tid & 31, warp = tid >> 5;
    int wm = warp >> 2, wn = warp & 3;
    int gq = lane >> 2, tg = lane & 3;
    int r0 = blockIdx.x * 64;
    sbc[tid] = g_bc[tid];

    float acc[2][4][2][4];
#pragma unroll
    for (int a = 0; a < 2; a++)
#pragma unroll
        for (int b = 0; b < 4; b++)
#pragma unroll
            for (int cc = 0; cc < 2; cc++)
#pragma unroll
                for (int d = 0; d < 4; d++) acc[a][b][cc][d] = 0.f;

    int arow = tid >> 2;
    int ac4 = (tid & 3) * 4;
    int akp = (tid & 3) * 2;
    bool rowok = (r0 + arow) < NN;
    const float* Abase = g_AH + (long)(r0 + arow) * KH + ac4;

    for (int k0 = 0; k0 < KH; k0 += BK) {
        float4 av = rowok ? *(const float4*)(Abase + k0) : make_float4(0.f, 0.f, 0.f, 0.f);
        unsigned h0, l0, h1, l1;
        bf16split2(av.x, av.y, h0, l0);
        bf16split2(av.z, av.w, h1, l1);
        Ah[arow][akp] = h0; Ah[arow][akp + 1] = h1;
        Al[arow][akp] = l0; Al[arow][akp + 1] = l1;
        int kp0 = (k0 >> 1);
#pragma unroll
        for (int i = 0; i < 2; i++) {
            int flat4 = i * 256 + tid;
            int kpl = flat4 >> 6, c4 = (flat4 & 63) * 4;
            uint4 bh = *(const uint4*)(g_Wgp_hi + (kp0 + kpl) * G4H + c4);
            uint4 bl = *(const uint4*)(g_Wgp_lo + (kp0 + kpl) * G4H + c4);
            Bh[kpl][c4 + 0] = bh.x; Bh[kpl][c4 + 1] = bh.y;
            Bh[kpl][c4 + 2] = bh.z; Bh[kpl][c4 + 3] = bh.w;
            Bl[kpl][c4 + 0] = bl.x; Bl[kpl][c4 + 1] = bl.y;
            Bl[kpl][c4 + 2] = bl.z; Bl[kpl][c4 + 3] = bl.w;
        }
        __syncthreads();

        unsigned ahi[2][4], alo[2][4];
#pragma unroll
        for (int mi = 0; mi < 2; mi++) {
            int rb = wm * 32 + mi * 16;
            ahi[mi][0] = Ah[rb + gq][tg];     alo[mi][0] = Al[rb + gq][tg];
            ahi[mi][1] = Ah[rb + gq + 8][tg]; alo[mi][1] = Al[rb + gq + 8][tg];
            ahi[mi][2] = Ah[rb + gq][tg + 4]; alo[mi][2] = Al[rb + gq][tg + 4];
            ahi[mi][3] = Ah[rb + gq + 8][tg + 4]; alo[mi][3] = Al[rb + gq + 8][tg + 4];
        }
#pragma unroll
        for (int gg = 0; gg < 4; gg++)
#pragma unroll
            for (int s = 0; s < 2; s++) {
                int cb = gg * 64 + wn * 16 + s * 8 + gq;
                unsigned bh0 = Bh[tg][cb], bh1 = Bh[tg + 4][cb];
                unsigned bl0 = Bl[tg][cb], bl1 = Bl[tg + 4][cb];
#pragma unroll
                for (int mi = 0; mi < 2; mi++) {
                    float* C = acc[mi][gg][s];
                    MMA_BF16(C[0], C[1], C[2], C[3],
                             alo[mi][0], alo[mi][1], alo[mi][2], alo[mi][3], bh0, bh1);
                    MMA_BF16(C[0], C[1], C[2], C[3],
                             ahi[mi][0], ahi[mi][1], ahi[mi][2], ahi[mi][3], bl0, bl1);
                    MMA_BF16(C[0], C[1], C[2], C[3],
                             ahi[mi][0], ahi[mi][1], ahi[mi][2], ahi[mi][3], bh0, bh1);
                }
            }
        __syncthreads();
    }

    // epilogue: + P[t] + bias, LSTM cell
#pragma unroll
    for (int mi = 0; mi < 2; mi++)
#pragma unroll
        for (int s = 0; s < 2; s++)
#pragma unroll
            for (int half = 0; half < 2; half++) {
                int row = r0 + wm * 32 + mi * 16 + gq + half * 8;
                if (row >= NN) continue;
                int j = wn * 16 + s * 8 + tg * 2;
                const float* Prow = g_P + ((long)t * NN + row) * G4H;
                float2 pi = *(const float2*)(Prow + j);
                float2 pf = *(const float2*)(Prow + 64 + j);
                float2 po = *(const float2*)(Prow + 128 + j);
                float2 pm = *(const float2*)(Prow + 192 + j);
                float2 cold = *(const float2*)(g_c + (long)row * 64 + j);
                float outc[2], outh[2];
#pragma unroll
                for (int cc = 0; cc < 2; cc++) {
                    int ri = half * 2 + cc;
                    float gi = acc[mi][0][s][ri] + (cc ? pi.y : pi.x) + sbc[j + cc];
                    float gf = acc[mi][1][s][ri] + (cc ? pf.y : pf.x) + sbc[64 + j + cc];
                    float go = acc[mi][2][s][ri] + (cc ? po.y : po.x) + sbc[128 + j + cc];
                    float gm = acc[mi][3][s][ri] + (cc ? pm.y : pm.x) + sbc[192 + j + cc];
                    float ii = sigm(gi), ff = sigm(gf), oo = sigm(go);
                    float mm = fmaxf(gm, 0.f);
                    float cv = tanhf(ii * mm + ff * (cc ? cold.y : cold.x));
                    outc[cc] = cv;
                    outh[cc] = oo * tanhf(cv);
                }
                *(float2*)(g_c + (long)row * 64 + j) = make_float2(outc[0], outc[1]);
                *(float2*)(g_h + (long)row * 64 + j) = make_float2(outh[0], outh[1]);
            }
}

// ---------------- DGPool ----------------
__global__ void k_vnorm(const float* __restrict__ pv) {
    __shared__ float red[64];
    int t = threadIdx.x;
    float v = pv[t];
    red[t] = v * v;
    __syncthreads();
    for (int s = 32; s > 0; s >>= 1) { if (t < s) red[t] += red[t + s]; __syncthreads(); }
    g_v[t] = v / (sqrtf(red[0]) + 1e-8f);
}

__global__ void k_scores() {
    __shared__ float ws[8];
    __shared__ int islast;
    int lane = threadIdx.x & 31, w = threadIdx.x >> 5;
    int n = blockIdx.x * 8 + w;
    float p = 0.f;
    if (n < NN)
        p = g_h[n * 64 + lane] * g_v[lane] + g_h[n * 64 + 32 + lane] * g_v[32 + lane];
    for (int o = 16; o; o >>= 1) p += __shfl_down_sync(0xffffffffu, p, o);
    if (lane == 0) {
        if (n < NN) g_raw[n] = p;
        ws[w] = (n < NN) ? p : 0.f;
    }
    __syncthreads();
    if (threadIdx.x == 0) {
        float s = 0.f, q = 0.f;
        for (int i = 0; i < 8; i++) { s += ws[i]; q += ws[i] * ws[i]; }
        atomicAdd(&g_ssum, s);
        atomicAdd(&g_ssq, q);
        __threadfence();
        islast = (atomicAdd(&g_sc_ticket, 1u) == gridDim.x - 1);
    }
    __syncthreads();
    if (islast && threadIdx.x == 0) {
        float fs = atomicAdd(&g_ssum, 0.f);
        float fq = atomicAdd(&g_ssq, 0.f);
        float mean = fs * (1.f / NN);
        float var = fq * (1.f / NN) - mean * mean;
        g_smean = mean;
        g_sinv = 1.f / (sqrtf(fmaxf(var, 0.f)) + 1e-8f);
        g_ssum = 0.f; g_ssq = 0.f; g_sc_ticket = 0u;
    }
}

__global__ void k_standardize(float* __restrict__ out) {
    int n = blockIdx.x * blockDim.x + threadIdx.x;
    float pl = 0.f;
    if (n < NN) {
        float s = (g_raw[n] - g_smean) * g_sinv;
        out[1 + n] = s;
        float sg = sigm(s);
        g_sig[n] = sg;
        unsigned u = __float_as_uint(s);
        u = (u & 0x80000000u) ? ~u : (u | 0x80000000u);
        g_key[n] = u;
        pl = sg * (1.f - sg);
    }
    for (int o = 16; o; o >>= 1) pl += __shfl_down_sync(0xffffffffu, pl, o);
    __shared__ float sred[8];
    if ((threadIdx.x & 31) == 0) sred[threadIdx.x >> 5] = pl;
    __syncthreads();
    if (threadIdx.x == 0) {
        float s = 0.f;
        for (int i = 0; i < 8; i++) s += sred[i];
        atomicAdd(&g_ploss, s);
    }
}

// single-block 4-pass radix select
__global__ void __launch_bounds__(1024) k_select() {
    __shared__ unsigned hist[256];
    __shared__ unsigned wsum[8];
    __shared__ unsigned s_prefix, s_kk;
    int t = threadIdx.x, lane = t & 31;
    if (t == 0) { s_prefix = 0u; s_kk = KSEL; }
#pragma unroll
    for (int pass = 0; pass < 4; pass++) {
        int shift = 24 - 8 * pass;
        if (t < 256) hist[t] = 0u;
        __syncthreads();
        unsigned pref = s_prefix;
        unsigned kk = s_kk;
        for (int i = t; i < NN; i += 1024) {
            unsigned k = g_key[i];
            bool cand = (pass == 0) || ((k >> (shift + 8)) == (pref >> (shift + 8)));
            if (cand) atomicAdd(&hist[(k >> shift) & 255u], 1u);
        }
        __syncthreads();
        unsigned x = 0, v = 0;
        if (t < 256) {
            int b = 255 - t;
            v = hist[b];
            x = v;
#pragma unroll
            for (int o = 1; o < 32; o <<= 1) {
                unsigned y = __shfl_up_sync(0xffffffffu, x, o);
                if (lane >= o) x += y;
            }
            if (lane == 31) wsum[t >> 5] = x;
        }
        __syncthreads();
        if (t < 256) {
            unsigned add = 0;
            int w = t >> 5;
            for (int j = 0; j < w; j++) add += wsum[j];
            unsigned S = x + add;
            unsigned Snext = S - v;
            if (S >= kk && Snext < kk) {
                s_prefix = pref | ((unsigned)(255 - t) << shift);
                s_kk = kk - Snext;
            }
        }
        __syncthreads();
    }
    if (t == 0) { g_prefix = s_prefix; g_kkleft = s_kk; }
}

__global__ void k_sumhigh() {
    __shared__ float acc[64];
    if (threadIdx.x < 64) acc[threadIdx.x] = 0.f;
    __syncthreads();
    int lane = threadIdx.x & 31, w = threadIdx.x >> 5;
    int n = blockIdx.x * 8 + w;
    if (n < NN) {
        int inc = 0;
        if (lane == 0) {
            unsigned key = g_key[n], tau = g_prefix;
            if (key > tau) inc = 1;
            else if (key == tau) {
                unsigned tk = atomicAdd(&g_ticket, 1u);
                inc = (tk < g_kkleft) ? 1 : 0;
            }
        }
        inc = __shfl_sync(0xffffffffu, inc, 0);
        if (inc) {
            float sg = g_sig[n];
            atomicAdd(&acc[lane],      g_h[n * 64 + lane] * sg);
            atomicAdd(&acc[lane + 32], g_h[n * 64 + lane + 32] * sg);
        }
    }
    __syncthreads();
    if (threadIdx.x < 64) atomicAdd(&g_high[threadIdx.x], acc[threadIdx.x]);
}

// ---------------- branch C: raw-fMRI LSTM ----------------
__global__ void k_Ggemm(const float* __restrict__ Wih, const float* __restrict__ ts) {
    __shared__ float sW[32][65];
    __shared__ float sT[32][51];
    int r0 = blockIdx.y * 64;
    int kbeg = blockIdx.x * KCH;
    int kend = min(NN, kbeg + KCH);
    int tid = threadIdx.x;
    int r = tid & 63, tq = tid >> 6;
    float acc[13];
#pragma unroll
    for (int j = 0; j < 13; j++) acc[j] = 0.f;

    for (int k0 = kbeg; k0 < kend; k0 += 32) {
#pragma unroll
        for (int i = 0; i < 8; i++) {
            int flat = i * 256 + tid;
            int kk = flat & 31, rr = flat >> 5;
            int kg = k0 + kk;
            sW[kk][rr] = (kg < kend) ? Wih[(long)(r0 + rr) * NN + kg] : 0.f;
        }
#pragma unroll
        for (int i = 0; i < 7; i++) {
            int flat = i * 256 + tid;
            if (flat < 1600) {
                int kk = flat & 31, t = flat >> 5;
                int kg = k0 + kk;
                sT[kk][t] = (kg < kend) ? ts[(long)t * NN + kg] : 0.f;
            }
        }
        __syncthreads();
#pragma unroll
        for (int kk = 0; kk < 32; kk++) {
            float wv = sW[kk][r];
#pragma unroll
            for (int j = 0; j < 13; j++) {
                int t = tq + 4 * j;
                if (t < TSN) acc[j] += wv * sT[kk][t];
            }
        }
        __syncthreads();
    }
#pragma unroll
    for (int j = 0; j < 13; j++) {
        int t = tq + 4 * j;
        if (t < TSN) atomicAdd(&g_G[t * G4H + r0 + r], acc[j]);
    }
}

__global__ void k_lstm(const float* __restrict__ Whh, const float* __restrict__ bih,
                       const float* __restrict__ bhh) {
    __shared__ float sh[64], scc[64], sg[256];
    int r = threadIdx.x;
    float wr[64];
#pragma unroll
    for (int m = 0; m < 64; m++) wr[m] = Whh[r * 64 + m];
    float bias = bih[r] + bhh[r];
    if (r < 64) { sh[r] = 0.f; scc[r] = 0.f; }
    __syncthreads();
    for (int t = 0; t < TSN; t++) {
        float a0 = 0.f, a1 = 0.f, a2 = 0.f, a3 = 0.f;
#pragma unroll
        for (int m = 0; m < 64; m += 4) {
            a0 += wr[m] * sh[m];
            a1 += wr[m + 1] * sh[m + 1];
            a2 += wr[m + 2] * sh[m + 2];
            a3 += wr[m + 3] * sh[m + 3];
        }
        float gv = g_G[t * G4H + r];
        g_G[t * G4H + r] = 0.f;   // reset for next replay
        sg[r] = gv + bias + ((a0 + a1) + (a2 + a3));
        __syncthreads();
        if (r < 64) {
            float gi = sg[r], gf = sg[64 + r], gg = sg[128 + r], go = sg[192 + r];
            float c = sigm(gf) * scc[r] + sigm(gi) * tanhf(gg);
            scc[r] = c;
            sh[r] = sigm(go) * tanhf(c);
        }
        __syncthreads();
    }
    if (r < 64) g_hl[r] = sh[r];
}

// ---------------- fusion head (+global resets for next replay) ----------------
__global__ void k_final(const float* __restrict__ lng, const float* __restrict__ lnb,
                        const float* __restrict__ W1, const float* __restrict__ b1,
                        const float* __restrict__ W2, const float* __restrict__ b2,
                        float* __restrict__ out) {
    __shared__ float red[128], sf[128], sz[64];
    int tid = threadIdx.x;
    float x = (tid < 64) ? g_high[tid] * (1.f / KSEL) : g_hl[tid - 64];
    if (tid < 64) g_high[tid] = 0.f;
    red[tid] = x;
    __syncthreads();
    for (int s = 64; s > 0; s >>= 1) { if (tid < s) red[tid] += red[tid + s]; __syncthreads(); }
    float mean = red[0] * (1.f / 128.f);
    __syncthreads();
    float d = x - mean;
    red[tid] = d * d;
    __syncthreads();
    for (int s = 64; s > 0; s >>= 1) { if (tid < s) red[tid] += red[tid + s]; __syncthreads(); }
    float var = red[0] * (1.f / 128.f);
    float y = d * rsqrtf(var + 1e-5f) * lng[tid] + lnb[tid];
    __syncthreads();
    sf[tid] = y;
    __syncthreads();
    if (tid < 64) {
        float a = b1[tid];
        for (int j = 0; j < 128; j++) a += sf[j] * W1[j * 64 + tid];
        sz[tid] = fmaxf(a, 0.f);
    }
    __syncthreads();
    red[tid] = (tid < 64) ? sz[tid] * W2[tid] : 0.f;
    __syncthreads();
    for (int s = 64; s > 0; s >>= 1) { if (tid < s) red[tid] += red[tid + s]; __syncthreads(); }
    if (tid == 0) {
        out[0] = red[0] + b2[0];
        out[NN + 1] = g_ploss * (1.f / NN);
        g_ploss = 0.f;
        g_ticket = 0u;
    }
}

// ---------------- launch (forked graph; streams/events created ONCE) ----------------
extern "C" void kernel_launch(void* const* d_in, const int* in_sizes, int n_in,
                              void* d_out, int out_size) {
    const float* xs   = (const float*)d_in[0];
    const void*  ei   = d_in[1];
    const float* ea   = (const float*)d_in[2];
    const float* h0   = (const float*)d_in[3];
    const float* c0   = (const float*)d_in[4];
    const float* ts   = (const float*)d_in[5];
    const float* Wrel = (const float*)d_in[6];
    const float* brel = (const float*)d_in[7];
    const float* Wroot= (const float*)d_in[8];
    const float* Wg   = (const float*)d_in[9];
    const float* bg   = (const float*)d_in[10];
    const float* pool = (const float*)d_in[11];
    const float* lng  = (const float*)d_in[12];
    const float* lnb  = (const float*)d_in[13];
    const float* Wih  = (const float*)d_in[14];
    const float* Whh  = (const float*)d_in[15];
    const float* bih  = (const float*)d_in[16];
    const float* bhh  = (const float*)d_in[17];
    const float* W1   = (const float*)d_in[18];
    const float* b1   = (const float*)d_in[19];
    const float* W2   = (const float*)d_in[20];
    const float* b2   = (const float*)d_in[21];
    float* out = (float*)d_out;

    static cudaStream_t sB = nullptr, sC = nullptr;
    static cudaEvent_t evFork = nullptr, evEdges = nullptr, evLstm = nullptr,
                       evV = nullptr, evAH0 = nullptr, evXG = nullptr,
                       evP1 = nullptr, evP2 = nullptr, evP3 = nullptr;
    if (sB == nullptr) {
        cudaStreamCreateWithFlags(&sB, cudaStreamNonBlocking);
        cudaStreamCreateWithFlags(&sC, cudaStreamNonBlocking);
        cudaEventCreateWithFlags(&evFork, cudaEventDisableTiming);
        cudaEventCreateWithFlags(&evEdges, cudaEventDisableTiming);
        cudaEventCreateWithFlags(&evLstm, cudaEventDisableTiming);
        cudaEventCreateWithFlags(&evV, cudaEventDisableTiming);
        cudaEventCreateWithFlags(&evAH0, cudaEventDisableTiming);
        cudaEventCreateWithFlags(&evXG, cudaEventDisableTiming);
        cudaEventCreateWithFlags(&evP1, cudaEventDisableTiming);
        cudaEventCreateWithFlags(&evP2, cudaEventDisableTiming);
        cudaEventCreateWithFlags(&evP3, cudaEventDisableTiming);
    }

    cudaEventRecord(evFork, 0);
    cudaStreamWaitEvent(sB, evFork, 0);
    cudaStreamWaitEvent(sC, evFork, 0);

    // branch B: edge structure + h/c init + t=0 agg_h gather (overlaps main prologue)
    k_decode<<<EE / 256, 256, 0, sB>>>(ei, h0, c0);
    k_prefix<<<1, 1024, 0, sB>>>();
    k_sortedges<<<EE / 256, 256, 0, sB>>>();
    cudaEventRecord(evEdges, sB);
    k_hgather<<<(NN * 32 + 255) / 256, 256, 0, sB>>>();
    cudaEventRecord(evAH0, sB);

    // branch C: pool-vec norm + fMRI LSTM (independent of main until scores/final)
    k_vnorm<<<1, 64, 0, sC>>>(pool);
    cudaEventRecord(evV, sC);
    k_Ggemm<<<dim3(128, 4), 256, 0, sC>>>(Wih, ts);
    k_lstm<<<1, 256, 0, sC>>>(Whh, bih, bhh);
    cudaEventRecord(evLstm, sC);

    // main branch
    k_colstats<<<dim3(40, TT), 256>>>(xs);
    k_prep<<<(TT * NN * FF) / 256, 256>>>(xs, Wrel, brel, Wroot, Wg, bg);
    cudaStreamWaitEvent(0, evEdges, 0);
    k_xgather<<<dim3((NN * 32 + 255) / 256, TT), 256>>>(ea);
    cudaEventRecord(evXG, 0);

    // biggemm chunked: t=0 rows on main; later timesteps on branch B with
    // per-chunk events so each hgemm(t) waits only for its own P rows.
    k_biggemm<<<CB0, 256>>>(0);
    cudaStreamWaitEvent(sB, evXG, 0);
    k_biggemm<<<CB1 - CB0, 256, 0, sB>>>(CB0);
    cudaEventRecord(evP1, sB);
    k_biggemm<<<CB2 - CB1, 256, 0, sB>>>(CB1);
    cudaEventRecord(evP2, sB);
    k_biggemm<<<NBALL - CB2, 256, 0, sB>>>(CB2);
    cudaEventRecord(evP3, sB);

    cudaStreamWaitEvent(0, evAH0, 0);
    k_hgemm<<<(NN + 63) / 64, 256>>>(0);   // t=0 AH pre-gathered on branch B
    k_hgather<<<(NN * 32 + 255) / 256, 256>>>();
    cudaStreamWaitEvent(0, evP1, 0);
    k_hgemm<<<(NN + 63) / 64, 256>>>(1);
    k_hgather<<<(NN * 32 + 255) / 256, 256>>>();
    cudaStreamWaitEvent(0, evP2, 0);
    k_hgemm<<<(NN + 63) / 64, 256>>>(2);
    k_hgather<<<(NN * 32 + 255) / 256, 256>>>();
    cudaStreamWaitEvent(0, evP3, 0);
    k_hgemm<<<(NN + 63) / 64, 256>>>(3);

    cudaStreamWaitEvent(0, evV, 0);
    k_scores<<<(NN + 7) / 8, 256>>>();
    k_standardize<<<(NN + 255) / 256, 256>>>(out);
    k_select<<<1, 1024>>>();
    k_sumhigh<<<(NN + 7) / 8, 256>>>();

    cudaStreamWaitEvent(0, evLstm, 0);
    k_final<<<1, 128>>>(lng, lnb, W1, b1, W2, b2, out);
}

// round 17
// speedup vs baseline: 1.1105x; 1.0177x over previous
#include <cuda_runtime.h>
#include <cuda_bf16.h>
#include <stdint.h>

#define TT   4
#define NN   20000
#define EE   320000
#define FF   64
#define HH   64
#define TSN  50
#define G4H  256
#define KX   128     // aggx(64) | xn(64)
#define KH   64      // aggh
#define KSEL 10000
#define BK   16
#define KCH  157     // Ggemm K-chunk: 128 splits * 157 >= 20000
#define NBALL 1250   // total biggemm blocks (TT*NN/64)
#define CB0  313     // blocks [0,313)    cover t=0 P rows
#define CB1  625     // blocks [313,625)  cover t=1 (with chunk0)
#define CB2  938     // blocks [625,938)  cover t=2 (with prior)

// ---------------- device scratch (zero-initialized at load) ----------------
__device__ __align__(16) float g_X[(long)TT * NN * KX];
__device__ __align__(16) float g_P[(long)TT * NN * G4H];
__device__ __align__(16) float g_AH[NN * KH];
__device__ __align__(16) float g_h[NN * HH];
__device__ __align__(16) float g_c[NN * HH];
__device__ float g_dinv[NN];
__device__ float g_self[NN];
__device__ __align__(16) int g_cnt[NN];
__device__ int   g_cursor[NN];
__device__ int   g_rowptr[NN + 1];
__device__ int   g_src[EE];
__device__ int   g_dst[EE];
__device__ int   g_s_src[EE];
__device__ int   g_s_eid[EE];
__device__ float g_s_gcn[EE];
__device__ __align__(16) unsigned g_Wxp_hi[(KX / 2) * G4H];
__device__ __align__(16) unsigned g_Wxp_lo[(KX / 2) * G4H];
__device__ __align__(16) unsigned g_Wgp_hi[(KH / 2) * G4H];
__device__ __align__(16) unsigned g_Wgp_lo[(KH / 2) * G4H];
__device__ __align__(16) float g_bc[G4H];
__device__ float g_colsum[TT * FF];
__device__ float g_colsq[TT * FF];
__device__ float g_mean[TT * FF];
__device__ float g_rinv[TT * FF];
__device__ float g_v[HH];
__device__ float g_raw[NN];
__device__ float g_sig[NN];
__device__ unsigned g_key[NN];
__device__ float g_high[HH];
__device__ __align__(16) float g_G[TSN * G4H];
__device__ float g_hl[HH];
__device__ unsigned g_prefix;
__device__ unsigned g_kkleft;
__device__ unsigned g_ticket;
__device__ unsigned g_cs_ticket[TT];
__device__ unsigned g_sc_ticket;
__device__ float g_ssum, g_ssq, g_smean, g_sinv, g_ploss;

__device__ __forceinline__ float sigm(float x) { return 1.f / (1.f + expf(-x)); }

// split (a,b) into packed bf16x2 hi + lo (2-term bf16 split; drops only lo*lo ~2^-18)
__device__ __forceinline__ void bf16split2(float a, float b, unsigned& hi, unsigned& lo) {
    __nv_bfloat16 ah = __float2bfloat16_rn(a);
    __nv_bfloat16 bh = __float2bfloat16_rn(b);
    float ar = a - __bfloat162float(ah);
    float br = b - __bfloat162float(bh);
    __nv_bfloat162 H; H.x = ah; H.y = bh;
    __nv_bfloat162 L; L.x = __float2bfloat16_rn(ar); L.y = __float2bfloat16_rn(br);
    hi = *(unsigned*)&H;
    lo = *(unsigned*)&L;
}

#define MMA_BF16(c0, c1, c2, c3, a0, a1, a2, a3, b0, b1)                         \
    asm volatile("mma.sync.aligned.m16n8k16.row.col.f32.bf16.bf16.f32 "          \
                 "{%0,%1,%2,%3}, {%4,%5,%6,%7}, {%8,%9}, {%0,%1,%2,%3};"         \
                 : "+f"(c0), "+f"(c1), "+f"(c2), "+f"(c3)                        \
                 : "r"(a0), "r"(a1), "r"(a2), "r"(a3), "r"(b0), "r"(b1))

// ---------------- branch B0: decode edges (+count) + copy h0/c0 ----------------
__global__ void k_decode(const void* eiraw, const float* __restrict__ h0,
                         const float* __restrict__ c0) {
    int gid = blockIdx.x * blockDim.x + threadIdx.x;   // exactly EE threads
    const long long* p64 = (const long long*)eiraw;
    bool is64 = true;
#pragma unroll
    for (int j = 0; j < 8; j++) {
        long long v = p64[j];
        if (v < 0 || v >= NN) is64 = false;
    }
    int s, d;
    if (is64) { s = (int)p64[gid]; d = (int)p64[EE + gid]; }
    else { const int* p32 = (const int*)eiraw; s = p32[gid]; d = p32[EE + gid]; }
    s = min(max(s, 0), NN - 1);
    d = min(max(d, 0), NN - 1);
    g_src[gid] = s;
    g_dst[gid] = d;
    atomicAdd(&g_cnt[d], 1);
    for (int j = gid; j < NN * HH; j += EE) { g_h[j] = h0[j]; g_c[j] = c0[j]; }
}

// ---------------- branch B1: fast single-block prefix scan + node norms ----------------
__global__ void k_prefix() {
    __shared__ int wsum[32];
    int t = threadIdx.x, lane = t & 31, wid = t >> 5;
    int vals[20];
    int s = 0;
    if (t < 1000) {
        const int4* p = (const int4*)(g_cnt + t * 20);
#pragma unroll
        for (int i = 0; i < 5; i++) {
            int4 v = p[i];
            vals[i * 4 + 0] = v.x; vals[i * 4 + 1] = v.y;
            vals[i * 4 + 2] = v.z; vals[i * 4 + 3] = v.w;
            s += v.x + v.y + v.z + v.w;
        }
    }
    int x = s;
#pragma unroll
    for (int o = 1; o < 32; o <<= 1) {
        int y = __shfl_up_sync(0xffffffffu, x, o);
        if (lane >= o) x += y;
    }
    if (lane == 31) wsum[wid] = x;
    __syncthreads();
    if (wid == 0) {
        int sv = wsum[lane];
#pragma unroll
        for (int o = 1; o < 32; o <<= 1) {
            int y = __shfl_up_sync(0xffffffffu, sv, o);
            if (lane >= o) sv += y;
        }
        wsum[lane] = sv;
    }
    __syncthreads();
    int excl = x - s + (wid > 0 ? wsum[wid - 1] : 0);
    if (t < 1000) {
        int run = excl;
#pragma unroll
        for (int j = 0; j < 20; j++) {
            int idx = t * 20 + j;
            g_rowptr[idx] = run;
            int v = vals[j];
            run += v;
            float dd = (float)v + 1.f;
            g_dinv[idx] = rsqrtf(dd);
            g_self[idx] = 1.f / dd;
            g_cnt[idx] = 0;   // reset for next replay
        }
    }
    if (t == 1023) g_rowptr[NN] = excl;
}

// ---------------- branch B2: bucket edges by destination ----------------
__global__ void k_sortedges() {
    int e = blockIdx.x * blockDim.x + threadIdx.x;
    if (e >= EE) return;
    int s = g_src[e], d = g_dst[e];
    int pos = g_rowptr[d] + atomicAdd(&g_cursor[d], 1);
    g_s_src[pos] = s;
    g_s_eid[pos] = e;
    g_s_gcn[pos] = g_dinv[s] * g_dinv[d];
}

// ---------------- agg_h gather (one warp per node) ----------------
__global__ void k_hgather() {
    int node = (blockIdx.x * blockDim.x + threadIdx.x) >> 5;
    int lane = threadIdx.x & 31;
    if (node >= NN) return;
    if (lane == 0) g_cursor[node] = 0;   // idempotent reset for next replay
    int beg = g_rowptr[node], end = g_rowptr[node + 1];
    float slf = g_self[node];
    float2 hv = ((const float2*)(g_h + (long)node * 64))[lane];
    float2 acc = make_float2(slf * hv.x, slf * hv.y);
    for (int e = beg; e < end; e++) {
        int s = g_s_src[e];
        float gn = g_s_gcn[e];
        float2 v = ((const float2*)(g_h + (long)s * 64))[lane];
        acc.x += gn * v.x;
        acc.y += gn * v.y;
    }
    ((float2*)(g_AH + (long)node * 64))[lane] = acc;
}

// ---------------- main A0: per-timestep column stats ----------------
__global__ void k_colstats(const float* __restrict__ xs) {
    __shared__ float ss[256], sq[256];
    __shared__ int islast;
    int t = blockIdx.y;
    const float* xt = xs + (long)t * NN * FF;
    int f = threadIdx.x & 63, slot = threadIdx.x >> 6;
    float s = 0.f, q = 0.f;
    for (int n = blockIdx.x * 4 + slot; n < NN; n += gridDim.x * 4) {
        float v = xt[n * 64 + f];
        s += v; q += v * v;
    }
    ss[threadIdx.x] = s; sq[threadIdx.x] = q;
    __syncthreads();
    if (slot == 0) {
        s = ss[f] + ss[f + 64] + ss[f + 128] + ss[f + 192];
        q = sq[f] + sq[f + 64] + sq[f + 128] + sq[f + 192];
        atomicAdd(&g_colsum[t * 64 + f], s);
        atomicAdd(&g_colsq[t * 64 + f], q);
    }
    __syncthreads();
    if (threadIdx.x == 0) {
        __threadfence();
        islast = (atomicAdd(&g_cs_ticket[t], 1u) == gridDim.x - 1);
    }
    __syncthreads();
    if (islast && threadIdx.x < 64) {
        int o = t * 64 + threadIdx.x;
        float fs = atomicAdd(&g_colsum[o], 0.f);
        float fq = atomicAdd(&g_colsq[o], 0.f);
        float mean = fs * (1.f / NN);
        float var = (fq - fs * fs * (1.f / NN)) * (1.f / (NN - 1));
        g_mean[o] = mean;
        g_rinv[o] = 1.f / (sqrtf(fmaxf(var, 0.f)) + 1e-6f);
        g_colsum[o] = 0.f;
        g_colsq[o] = 0.f;
        if (threadIdx.x == 0) g_cs_ticket[t] = 0u;
    }
}

// ---------------- main A1: normalize x (all T) + pack/split weights ----------------
__global__ void k_prep(const float* __restrict__ xs,
                       const float* __restrict__ Wrel, const float* __restrict__ brel,
                       const float* __restrict__ Wroot, const float* __restrict__ Wg,
                       const float* __restrict__ bg) {
    int gid = blockIdx.x * blockDim.x + threadIdx.x;   // TT*NN*FF threads
    int t = gid / (NN * FF);
    int rem = gid - t * (NN * FF);
    int n = rem >> 6, f = rem & 63;
    float xn = (xs[gid] - g_mean[t * 64 + f]) * g_rinv[t * 64 + f];
    g_X[((long)t * NN + n) * KX + 64 + f] = xn;

    if (gid < (KX / 2) * G4H) {
        int kp = gid >> 8, col = gid & 255;
        int g = col >> 6, h2 = col & 63;
        int k0 = 2 * kp, k1 = 2 * kp + 1;
        float w0 = (k0 < 64) ? Wrel[g * 4096 + k0 * 64 + h2]
                             : Wroot[g * 4096 + (k0 - 64) * 64 + h2];
        float w1 = (k1 < 64) ? Wrel[g * 4096 + k1 * 64 + h2]
                             : Wroot[g * 4096 + (k1 - 64) * 64 + h2];
        unsigned hi, lo;
        bf16split2(w0, w1, hi, lo);
        g_Wxp_hi[gid] = hi; g_Wxp_lo[gid] = lo;
    }
    if (gid < (KH / 2) * G4H) {
        int kp = gid >> 8, col = gid & 255;
        int g = col >> 6, h2 = col & 63;
        unsigned hi, lo;
        bf16split2(Wg[g * 4096 + (2 * kp) * 64 + h2],
                   Wg[g * 4096 + (2 * kp + 1) * 64 + h2], hi, lo);
        g_Wgp_hi[gid] = hi; g_Wgp_lo[gid] = lo;
    }
    if (gid < G4H) g_bc[gid] = brel[gid] + bg[gid];
}

// ---------------- main A2: agg_x gather, one warp per (node, t); tbase selects slice ----------------
__global__ void k_xgather(const float* __restrict__ ea, int tbase) {
    int node = (blockIdx.x * blockDim.x + threadIdx.x) >> 5;
    int t = tbase + blockIdx.y;
    int lane = threadIdx.x & 31;
    if (node >= NN) return;
    int beg = g_rowptr[node], end = g_rowptr[node + 1];
    const float* eat = ea + (long)t * EE;
    float* Xt = g_X + (long)t * NN * KX;
    float2 acc = make_float2(0.f, 0.f);
    for (int e = beg; e < end; e++) {
        int s = g_s_src[e];
        float w = eat[g_s_eid[e]];
        float2 v = ((const float2*)(Xt + (long)s * KX + 64))[lane];
        acc.x += w * v.x;
        acc.y += w * v.y;
    }
    ((float2*)(Xt + (long)node * KX))[lane] = acc;
}

// ---------------- main A3: big batched GEMM  P = X[80000,128] @ Wx[128,256] (3xBF16)
// Launched in chunks via blk0 offset for fine-grained overlap with the h-loop.
__global__ void __launch_bounds__(256) k_biggemm(int blk0) {
    __shared__ unsigned Ah[64][12], Al[64][12];
    __shared__ unsigned Bh[8][264], Bl[8][264];
    int tid = threadIdx.x;
    int lane = tid & 31, warp = tid >> 5;
    int wm = warp >> 2, wn = warp & 3;
    int gq = lane >> 2, tg = lane & 3;
    long r0 = (long)(blk0 + blockIdx.x) * 64;

    float acc[2][4][2][4];
#pragma unroll
    for (int a = 0; a < 2; a++)
#pragma unroll
        for (int b = 0; b < 4; b++)
#pragma unroll
            for (int cc = 0; cc < 2; cc++)
#pragma unroll
                for (int d = 0; d < 4; d++) acc[a][b][cc][d] = 0.f;

    int arow = tid >> 2;
    int ac4 = (tid & 3) * 4;
    int akp = (tid & 3) * 2;
    const float* Abase = g_X + (r0 + arow) * KX + ac4;

    for (int k0 = 0; k0 < KX; k0 += BK) {
        float4 av = *(const float4*)(Abase + k0);
        unsigned h0, l0, h1, l1;
        bf16split2(av.x, av.y, h0, l0);
        bf16split2(av.z, av.w, h1, l1);
        Ah[arow][akp] = h0; Ah[arow][akp + 1] = h1;
        Al[arow][akp] = l0; Al[arow][akp + 1] = l1;
        int kp0 = (k0 >> 1);
#pragma unroll
        for (int i = 0; i < 2; i++) {
            int flat4 = i * 256 + tid;
            int kpl = flat4 >> 6, c4 = (flat4 & 63) * 4;
            uint4 bh = *(const uint4*)(g_Wxp_hi + (kp0 + kpl) * G4H + c4);
            uint4 bl = *(const uint4*)(g_Wxp_lo + (kp0 + kpl) * G4H + c4);
            Bh[kpl][c4 + 0] = bh.x; Bh[kpl][c4 + 1] = bh.y;
            Bh[kpl][c4 + 2] = bh.z; Bh[kpl][c4 + 3] = bh.w;
            Bl[kpl][c4 + 0] = bl.x; Bl[kpl][c4 + 1] = bl.y;
            Bl[kpl][c4 + 2] = bl.z; Bl[kpl][c4 + 3] = bl.w;
        }
        __syncthreads();

        unsigned ahi[2][4], alo[2][4];
#pragma unroll
        for (int mi = 0; mi < 2; mi++) {
            int rb = wm * 32 + mi * 16;
            ahi[mi][0] = Ah[rb + gq][tg];     alo[mi][0] = Al[rb + gq][tg];
            ahi[mi][1] = Ah[rb + gq + 8][tg]; alo[mi][1] = Al[rb + gq + 8][tg];
            ahi[mi][2] = Ah[rb + gq][tg + 4]; alo[mi][2] = Al[rb + gq][tg + 4];
            ahi[mi][3] = Ah[rb + gq + 8][tg + 4]; alo[mi][3] = Al[rb + gq + 8][tg + 4];
        }
#pragma unroll
        for (int gg = 0; gg < 4; gg++)
#pragma unroll
            for (int s = 0; s < 2; s++) {
                int cb = gg * 64 + wn * 16 + s * 8 + gq;
                unsigned bh0 = Bh[tg][cb], bh1 = Bh[tg + 4][cb];
                unsigned bl0 = Bl[tg][cb], bl1 = Bl[tg + 4][cb];
#pragma unroll
                for (int mi = 0; mi < 2; mi++) {
                    float* C = acc[mi][gg][s];
                    MMA_BF16(C[0], C[1], C[2], C[3],
                             alo[mi][0], alo[mi][1], alo[mi][2], alo[mi][3], bh0, bh1);
                    MMA_BF16(C[0], C[1], C[2], C[3],
                             ahi[mi][0], ahi[mi][1], ahi[mi][2], ahi[mi][3], bl0, bl1);
                    MMA_BF16(C[0], C[1], C[2], C[3],
                             ahi[mi][0], ahi[mi][1], ahi[mi][2], ahi[mi][3], bh0, bh1);
                }
            }
        __syncthreads();
    }
#pragma unroll
    for (int mi = 0; mi < 2; mi++)
#pragma unroll
        for (int gg = 0; gg < 4; gg++)
#pragma unroll
            for (int s = 0; s < 2; s++)
#pragma unroll
                for (int half = 0; half < 2; half++) {
                    long row = r0 + wm * 32 + mi * 16 + gq + half * 8;
                    int j = gg * 64 + wn * 16 + s * 8 + tg * 2;
                    float2 v = make_float2(acc[mi][gg][s][half * 2 + 0],
                                           acc[mi][gg][s][half * 2 + 1]);
                    *(float2*)(g_P + row * G4H + j) = v;
                }
}

// ---------------- loop: gates = AH[NN,64]@Wg + P[t] + bc, fused cell (3xBF16) ----------------
__global__ void __launch_bounds__(256) k_hgemm(int t) {
    __shared__ unsigned Ah[64][12], Al[64][12];
    __shared__ unsigned Bh[8][264], Bl[8][264];
    __shared__ float sbc[256];
    int tid = threadIdx.x;
    int lane = tid & 31, warp = tid >> 5;
    int wm = warp >> 2, wn = warp & 3;
    int gq = lane >> 2, tg = lane & 3;
    int r0 = blockIdx.x * 64;
    sbc[tid] = g_bc[tid];

    float acc[2][4][2][4];
#pragma unroll
    for (int a = 0; a < 2; a++)
#pragma unroll
        for (int b = 0; b < 4; b++)
#pragma unroll
            for (int cc = 0; cc < 2; cc++)
#pragma unroll
                for (int d = 0; d < 4; d++) acc[a][b][cc][d] = 0.f;

    int arow = tid >> 2;
    int ac4 = (tid & 3) * 4;
    int akp = (tid & 3) * 2;
    bool rowok = (r0 + arow) < NN;
    const float* Abase = g_AH + (long)(r0 + arow) * KH + ac4;

    for (int k0 = 0; k0 < KH; k0 += BK) {
        float4 av = rowok ? *(const float4*)(Abase + k0) : make_float4(0.f, 0.f, 0.f, 0.f);
        unsigned h0, l0, h1, l1;
        bf16split2(av.x, av.y, h0, l0);
        bf16split2(av.z, av.w, h1, l1);
        Ah[arow][akp] = h0; Ah[arow][akp + 1] = h1;
        Al[arow][akp] = l0; Al[arow][akp + 1] = l1;
        int kp0 = (k0 >> 1);
#pragma unroll
        for (int i = 0; i < 2; i++) {
            int flat4 = i * 256 + tid;
            int kpl = flat4 >> 6, c4 = (flat4 & 63) * 4;
            uint4 bh = *(const uint4*)(g_Wgp_hi + (kp0 + kpl) * G4H + c4);
            uint4 bl = *(const uint4*)(g_Wgp_lo + (kp0 + kpl) * G4H + c4);
            Bh[kpl][c4 + 0] = bh.x; Bh[kpl][c4 + 1] = bh.y;
            Bh[kpl][c4 + 2] = bh.z; Bh[kpl][c4 + 3] = bh.w;
            Bl[kpl][c4 + 0] = bl.x; Bl[kpl][c4 + 1] = bl.y;
            Bl[kpl][c4 + 2] = bl.z; Bl[kpl][c4 + 3] = bl.w;
        }
        __syncthreads();

        unsigned ahi[2][4], alo[2][4];
#pragma unroll
        for (int mi = 0; mi < 2; mi++) {
            int rb = wm * 32 + mi * 16;
            ahi[mi][0] = Ah[rb + gq][tg];     alo[mi][0] = Al[rb + gq][tg];
            ahi[mi][1] = Ah[rb + gq + 8][tg]; alo[mi][1] = Al[rb + gq + 8][tg];
            ahi[mi][2] = Ah[rb + gq][tg + 4]; alo[mi][2] = Al[rb + gq][tg + 4];
            ahi[mi][3] = Ah[rb + gq + 8][tg + 4]; alo[mi][3] = Al[rb + gq + 8][tg + 4];
        }
#pragma unroll
        for (int gg = 0; gg < 4; gg++)
#pragma unroll
            for (int s = 0; s < 2; s++) {
                int cb = gg * 64 + wn * 16 + s * 8 + gq;
                unsigned bh0 = Bh[tg][cb], bh1 = Bh[tg + 4][cb];
                unsigned bl0 = Bl[tg][cb], bl1 = Bl[tg + 4][cb];
#pragma unroll
                for (int mi = 0; mi < 2; mi++) {
                    float* C = acc[mi][gg][s];
                    MMA_BF16(C[0], C[1], C[2], C[3],
                             alo[mi][0], alo[mi][1], alo[mi][2], alo[mi][3], bh0, bh1);
                    MMA_BF16(C[0], C[1], C[2], C[3],
                             ahi[mi][0], ahi[mi][1], ahi[mi][2], ahi[mi][3], bl0, bl1);
                    MMA_BF16(C[0], C[1], C[2], C[3],
                             ahi[mi][0], ahi[mi][1], ahi[mi][2], ahi[mi][3], bh0, bh1);
                }
            }
        __syncthreads();
    }

    // epilogue: + P[t] + bias, LSTM cell
#pragma unroll
    for (int mi = 0; mi < 2; mi++)
#pragma unroll
        for (int s = 0; s < 2; s++)
#pragma unroll
            for (int half = 0; half < 2; half++) {
                int row = r0 + wm * 32 + mi * 16 + gq + half * 8;
                if (row >= NN) continue;
                int j = wn * 16 + s * 8 + tg * 2;
                const float* Prow = g_P + ((long)t * NN + row) * G4H;
                float2 pi = *(const float2*)(Prow + j);
                float2 pf = *(const float2*)(Prow + 64 + j);
                float2 po = *(const float2*)(Prow + 128 + j);
                float2 pm = *(const float2*)(Prow + 192 + j);
                float2 cold = *(const float2*)(g_c + (long)row * 64 + j);
                float outc[2], outh[2];
#pragma unroll
                for (int cc = 0; cc < 2; cc++) {
                    int ri = half * 2 + cc;
                    float gi = acc[mi][0][s][ri] + (cc ? pi.y : pi.x) + sbc[j + cc];
                    float gf = acc[mi][1][s][ri] + (cc ? pf.y : pf.x) + sbc[64 + j + cc];
                    float go = acc[mi][2][s][ri] + (cc ? po.y : po.x) + sbc[128 + j + cc];
                    float gm = acc[mi][3][s][ri] + (cc ? pm.y : pm.x) + sbc[192 + j + cc];
                    float ii = sigm(gi), ff = sigm(gf), oo = sigm(go);
                    float mm = fmaxf(gm, 0.f);
                    float cv = tanhf(ii * mm + ff * (cc ? cold.y : cold.x));
                    outc[cc] = cv;
                    outh[cc] = oo * tanhf(cv);
                }
                *(float2*)(g_c + (long)row * 64 + j) = make_float2(outc[0], outc[1]);
                *(float2*)(g_h + (long)row * 64 + j) = make_float2(outh[0], outh[1]);
            }
}

// ---------------- DGPool ----------------
__global__ void k_vnorm(const float* __restrict__ pv) {
    __shared__ float red[64];
    int t = threadIdx.x;
    float v = pv[t];
    red[t] = v * v;
    __syncthreads();
    for (int s = 32; s > 0; s >>= 1) { if (t < s) red[t] += red[t + s]; __syncthreads(); }
    g_v[t] = v / (sqrtf(red[0]) + 1e-8f);
}

__global__ void k_scores() {
    __shared__ float ws[8];
    __shared__ int islast;
    int lane = threadIdx.x & 31, w = threadIdx.x >> 5;
    int n = blockIdx.x * 8 + w;
    float p = 0.f;
    if (n < NN)
        p = g_h[n * 64 + lane] * g_v[lane] + g_h[n * 64 + 32 + lane] * g_v[32 + lane];
    for (int o = 16; o; o >>= 1) p += __shfl_down_sync(0xffffffffu, p, o);
    if (lane == 0) {
        if (n < NN) g_raw[n] = p;
        ws[w] = (n < NN) ? p : 0.f;
    }
    __syncthreads();
    if (threadIdx.x == 0) {
        float s = 0.f, q = 0.f;
        for (int i = 0; i < 8; i++) { s += ws[i]; q += ws[i] * ws[i]; }
        atomicAdd(&g_ssum, s);
        atomicAdd(&g_ssq, q);
        __threadfence();
        islast = (atomicAdd(&g_sc_ticket, 1u) == gridDim.x - 1);
    }
    __syncthreads();
    if (islast && threadIdx.x == 0) {
        float fs = atomicAdd(&g_ssum, 0.f);
        float fq = atomicAdd(&g_ssq, 0.f);
        float mean = fs * (1.f / NN);
        float var = fq * (1.f / NN) - mean * mean;
        g_smean = mean;
        g_sinv = 1.f / (sqrtf(fmaxf(var, 0.f)) + 1e-8f);
        g_ssum = 0.f; g_ssq = 0.f; g_sc_ticket = 0u;
    }
}

__global__ void k_standardize(float* __restrict__ out) {
    int n = blockIdx.x * blockDim.x + threadIdx.x;
    float pl = 0.f;
    if (n < NN) {
        float s = (g_raw[n] - g_smean) * g_sinv;
        out[1 + n] = s;
        float sg = sigm(s);
        g_sig[n] = sg;
        unsigned u = __float_as_uint(s);
        u = (u & 0x80000000u) ? ~u : (u | 0x80000000u);
        g_key[n] = u;
        pl = sg * (1.f - sg);
    }
    for (int o = 16; o; o >>= 1) pl += __shfl_down_sync(0xffffffffu, pl, o);
    __shared__ float sred[8];
    if ((threadIdx.x & 31) == 0) sred[threadIdx.x >> 5] = pl;
    __syncthreads();
    if (threadIdx.x == 0) {
        float s = 0.f;
        for (int i = 0; i < 8; i++) s += sred[i];
        atomicAdd(&g_ploss, s);
    }
}

// single-block 4-pass radix select
__global__ void __launch_bounds__(1024) k_select() {
    __shared__ unsigned hist[256];
    __shared__ unsigned wsum[8];
    __shared__ unsigned s_prefix, s_kk;
    int t = threadIdx.x, lane = t & 31;
    if (t == 0) { s_prefix = 0u; s_kk = KSEL; }
#pragma unroll
    for (int pass = 0; pass < 4; pass++) {
        int shift = 24 - 8 * pass;
        if (t < 256) hist[t] = 0u;
        __syncthreads();
        unsigned pref = s_prefix;
        unsigned kk = s_kk;
        for (int i = t; i < NN; i += 1024) {
            unsigned k = g_key[i];
            bool cand = (pass == 0) || ((k >> (shift + 8)) == (pref >> (shift + 8)));
            if (cand) atomicAdd(&hist[(k >> shift) & 255u], 1u);
        }
        __syncthreads();
        unsigned x = 0, v = 0;
        if (t < 256) {
            int b = 255 - t;
            v = hist[b];
            x = v;
#pragma unroll
            for (int o = 1; o < 32; o <<= 1) {
                unsigned y = __shfl_up_sync(0xffffffffu, x, o);
                if (lane >= o) x += y;
            }
            if (lane == 31) wsum[t >> 5] = x;
        }
        __syncthreads();
        if (t < 256) {
            unsigned add = 0;
            int w = t >> 5;
            for (int j = 0; j < w; j++) add += wsum[j];
            unsigned S = x + add;
            unsigned Snext = S - v;
            if (S >= kk && Snext < kk) {
                s_prefix = pref | ((unsigned)(255 - t) << shift);
                s_kk = kk - Snext;
            }
        }
        __syncthreads();
    }
    if (t == 0) { g_prefix = s_prefix; g_kkleft = s_kk; }
}

__global__ void k_sumhigh() {
    __shared__ float acc[64];
    if (threadIdx.x < 64) acc[threadIdx.x] = 0.f;
    __syncthreads();
    int lane = threadIdx.x & 31, w = threadIdx.x >> 5;
    int n = blockIdx.x * 8 + w;
    if (n < NN) {
        int inc = 0;
        if (lane == 0) {
            unsigned key = g_key[n], tau = g_prefix;
            if (key > tau) inc = 1;
            else if (key == tau) {
                unsigned tk = atomicAdd(&g_ticket, 1u);
                inc = (tk < g_kkleft) ? 1 : 0;
            }
        }
        inc = __shfl_sync(0xffffffffu, inc, 0);
        if (inc) {
            float sg = g_sig[n];
            atomicAdd(&acc[lane],      g_h[n * 64 + lane] * sg);
            atomicAdd(&acc[lane + 32], g_h[n * 64 + lane + 32] * sg);
        }
    }
    __syncthreads();
    if (threadIdx.x < 64) atomicAdd(&g_high[threadIdx.x], acc[threadIdx.x]);
}

// ---------------- branch C: raw-fMRI LSTM ----------------
__global__ void k_Ggemm(const float* __restrict__ Wih, const float* __restrict__ ts) {
    __shared__ float sW[32][65];
    __shared__ float sT[32][51];
    int r0 = blockIdx.y * 64;
    int kbeg = blockIdx.x * KCH;
    int kend = min(NN, kbeg + KCH);
    int tid = threadIdx.x;
    int r = tid & 63, tq = tid >> 6;
    float acc[13];
#pragma unroll
    for (int j = 0; j < 13; j++) acc[j] = 0.f;

    for (int k0 = kbeg; k0 < kend; k0 += 32) {
#pragma unroll
        for (int i = 0; i < 8; i++) {
            int flat = i * 256 + tid;
            int kk = flat & 31, rr = flat >> 5;
            int kg = k0 + kk;
            sW[kk][rr] = (kg < kend) ? Wih[(long)(r0 + rr) * NN + kg] : 0.f;
        }
#pragma unroll
        for (int i = 0; i < 7; i++) {
            int flat = i * 256 + tid;
            if (flat < 1600) {
                int kk = flat & 31, t = flat >> 5;
                int kg = k0 + kk;
                sT[kk][t] = (kg < kend) ? ts[(long)t * NN + kg] : 0.f;
            }
        }
        __syncthreads();
#pragma unroll
        for (int kk = 0; kk < 32; kk++) {
            float wv = sW[kk][r];
#pragma unroll
            for (int j = 0; j < 13; j++) {
                int t = tq + 4 * j;
                if (t < TSN) acc[j] += wv * sT[kk][t];
            }
        }
        __syncthreads();
    }
#pragma unroll
    for (int j = 0; j < 13; j++) {
        int t = tq + 4 * j;
        if (t < TSN) atomicAdd(&g_G[t * G4H + r0 + r], acc[j]);
    }
}

__global__ void k_lstm(const float* __restrict__ Whh, const float* __restrict__ bih,
                       const float* __restrict__ bhh) {
    __shared__ float sh[64], scc[64], sg[256];
    int r = threadIdx.x;
    float wr[64];
#pragma unroll
    for (int m = 0; m < 64; m++) wr[m] = Whh[r * 64 + m];
    float bias = bih[r] + bhh[r];
    if (r < 64) { sh[r] = 0.f; scc[r] = 0.f; }
    __syncthreads();
    for (int t = 0; t < TSN; t++) {
        float a0 = 0.f, a1 = 0.f, a2 = 0.f, a3 = 0.f;
#pragma unroll
        for (int m = 0; m < 64; m += 4) {
            a0 += wr[m] * sh[m];
            a1 += wr[m + 1] * sh[m + 1];
            a2 += wr[m + 2] * sh[m + 2];
            a3 += wr[m + 3] * sh[m + 3];
        }
        float gv = g_G[t * G4H + r];
        g_G[t * G4H + r] = 0.f;   // reset for next replay
        sg[r] = gv + bias + ((a0 + a1) + (a2 + a3));
        __syncthreads();
        if (r < 64) {
            float gi = sg[r], gf = sg[64 + r], gg = sg[128 + r], go = sg[192 + r];
            float c = sigm(gf) * scc[r] + sigm(gi) * tanhf(gg);
            scc[r] = c;
            sh[r] = sigm(go) * tanhf(c);
        }
        __syncthreads();
    }
    if (r < 64) g_hl[r] = sh[r];
}

// ---------------- fusion head (+global resets for next replay) ----------------
__global__ void k_final(const float* __restrict__ lng, const float* __restrict__ lnb,
                        const float* __restrict__ W1, const float* __restrict__ b1,
                        const float* __restrict__ W2, const float* __restrict__ b2,
                        float* __restrict__ out) {
    __shared__ float red[128], sf[128], sz[64];
    int tid = threadIdx.x;
    float x = (tid < 64) ? g_high[tid] * (1.f / KSEL) : g_hl[tid - 64];
    if (tid < 64) g_high[tid] = 0.f;
    red[tid] = x;
    __syncthreads();
    for (int s = 64; s > 0; s >>= 1) { if (tid < s) red[tid] += red[tid + s]; __syncthreads(); }
    float mean = red[0] * (1.f / 128.f);
    __syncthreads();
    float d = x - mean;
    red[tid] = d * d;
    __syncthreads();
    for (int s = 64; s > 0; s >>= 1) { if (tid < s) red[tid] += red[tid + s]; __syncthreads(); }
    float var = red[0] * (1.f / 128.f);
    float y = d * rsqrtf(var + 1e-5f) * lng[tid] + lnb[tid];
    __syncthreads();
    sf[tid] = y;
    __syncthreads();
    if (tid < 64) {
        float a = b1[tid];
        for (int j = 0; j < 128; j++) a += sf[j] * W1[j * 64 + tid];
        sz[tid] = fmaxf(a, 0.f);
    }
    __syncthreads();
    red[tid] = (tid < 64) ? sz[tid] * W2[tid] : 0.f;
    __syncthreads();
    for (int s = 64; s > 0; s >>= 1) { if (tid < s) red[tid] += red[tid + s]; __syncthreads(); }
    if (tid == 0) {
        out[0] = red[0] + b2[0];
        out[NN + 1] = g_ploss * (1.f / NN);
        g_ploss = 0.f;
        g_ticket = 0u;
    }
}

// ---------------- launch (forked graph; streams/events created ONCE) ----------------
extern "C" void kernel_launch(void* const* d_in, const int* in_sizes, int n_in,
                              void* d_out, int out_size) {
    const float* xs   = (const float*)d_in[0];
    const void*  ei   = d_in[1];
    const float* ea   = (const float*)d_in[2];
    const float* h0   = (const float*)d_in[3];
    const float* c0   = (const float*)d_in[4];
    const float* ts   = (const float*)d_in[5];
    const float* Wrel = (const float*)d_in[6];
    const float* brel = (const float*)d_in[7];
    const float* Wroot= (const float*)d_in[8];
    const float* Wg   = (const float*)d_in[9];
    const float* bg   = (const float*)d_in[10];
    const float* pool = (const float*)d_in[11];
    const float* lng  = (const float*)d_in[12];
    const float* lnb  = (const float*)d_in[13];
    const float* Wih  = (const float*)d_in[14];
    const float* Whh  = (const float*)d_in[15];
    const float* bih  = (const float*)d_in[16];
    const float* bhh  = (const float*)d_in[17];
    const float* W1   = (const float*)d_in[18];
    const float* b1   = (const float*)d_in[19];
    const float* W2   = (const float*)d_in[20];
    const float* b2   = (const float*)d_in[21];
    float* out = (float*)d_out;

    static cudaStream_t sB = nullptr, sC = nullptr;
    static cudaEvent_t evFork = nullptr, evEdges = nullptr, evLstm = nullptr,
                       evV = nullptr, evAH0 = nullptr, evPrep = nullptr,
                       evP1 = nullptr, evP2 = nullptr, evP3 = nullptr;
    if (sB == nullptr) {
        cudaStreamCreateWithFlags(&sB, cudaStreamNonBlocking);
        cudaStreamCreateWithFlags(&sC, cudaStreamNonBlocking);
        cudaEventCreateWithFlags(&evFork, cudaEventDisableTiming);
        cudaEventCreateWithFlags(&evEdges, cudaEventDisableTiming);
        cudaEventCreateWithFlags(&evLstm, cudaEventDisableTiming);
        cudaEventCreateWithFlags(&evV, cudaEventDisableTiming);
        cudaEventCreateWithFlags(&evAH0, cudaEventDisableTiming);
        cudaEventCreateWithFlags(&evPrep, cudaEventDisableTiming);
        cudaEventCreateWithFlags(&evP1, cudaEventDisableTiming);
        cudaEventCreateWithFlags(&evP2, cudaEventDisableTiming);
        cudaEventCreateWithFlags(&evP3, cudaEventDisableTiming);
    }

    cudaEventRecord(evFork, 0);
    cudaStreamWaitEvent(sB, evFork, 0);
    cudaStreamWaitEvent(sC, evFork, 0);

    // branch B: edge structure + h/c init + t=0 agg_h gather (overlaps main prologue)
    k_decode<<<EE / 256, 256, 0, sB>>>(ei, h0, c0);
    k_prefix<<<1, 1024, 0, sB>>>();
    k_sortedges<<<EE / 256, 256, 0, sB>>>();
    cudaEventRecord(evEdges, sB);
    k_hgather<<<(NN * 32 + 255) / 256, 256, 0, sB>>>();
    cudaEventRecord(evAH0, sB);

    // branch C: pool-vec norm + fMRI LSTM (independent of main until scores/final)
    k_vnorm<<<1, 64, 0, sC>>>(pool);
    cudaEventRecord(evV, sC);
    k_Ggemm<<<dim3(128, 4), 256, 0, sC>>>(Wih, ts);
    k_lstm<<<1, 256, 0, sC>>>(Whh, bih, bhh);
    cudaEventRecord(evLstm, sC);

    // main branch
    k_colstats<<<dim3(40, TT), 256>>>(xs);
    k_prep<<<(TT * NN * FF) / 256, 256>>>(xs, Wrel, brel, Wroot, Wg, bg);
    cudaEventRecord(evPrep, 0);
    cudaStreamWaitEvent(0, evEdges, 0);
    // xgather t=0 only on the critical path; chunk0 follows immediately
    k_xgather<<<dim3((NN * 32 + 255) / 256, 1), 256>>>(ea, 0);
    k_biggemm<<<CB0, 256>>>(0);

    // branch B (after its t=0 hgather): xgather t=1..3, then biggemm chunks 1..3
    cudaStreamWaitEvent(sB, evPrep, 0);
    k_xgather<<<dim3((NN * 32 + 255) / 256, 3), 256, 0, sB>>>(ea, 1);
    k_biggemm<<<CB1 - CB0, 256, 0, sB>>>(CB0);
    cudaEventRecord(evP1, sB);
    k_biggemm<<<CB2 - CB1, 256, 0, sB>>>(CB1);
    cudaEventRecord(evP2, sB);
    k_biggemm<<<NBALL - CB2, 256, 0, sB>>>(CB2);
    cudaEventRecord(evP3, sB);

    cudaStreamWaitEvent(0, evAH0, 0);
    k_hgemm<<<(NN + 63) / 64, 256>>>(0);   // t=0 AH pre-gathered on branch B
    k_hgather<<<(NN * 32 + 255) / 256, 256>>>();
    cudaStreamWaitEvent(0, evP1, 0);
    k_hgemm<<<(NN + 63) / 64, 256>>>(1);
    k_hgather<<<(NN * 32 + 255) / 256, 256>>>();
    cudaStreamWaitEvent(0, evP2, 0);
    k_hgemm<<<(NN + 63) / 64, 256>>>(2);
    k_hgather<<<(NN * 32 + 255) / 256, 256>>>();
    cudaStreamWaitEvent(0, evP3, 0);
    k_hgemm<<<(NN + 63) / 64, 256>>>(3);

    cudaStreamWaitEvent(0, evV, 0);
    k_scores<<<(NN + 7) / 8, 256>>>();
    k_standardize<<<(NN + 255) / 256, 256>>>(out);
    k_select<<<1, 1024>>>();
    k_sumhigh<<<(NN + 7) / 8, 256>>>();

    cudaStreamWaitEvent(0, evLstm, 0);
    k_final<<<1, 128>>>(lng, lnb, W1, b1, W2, b2, out);
}